// round 14
// baseline (speedup 1.0000x reference)
#include <cuda_runtime.h>
#include <cuda_bf16.h>
#include <math.h>
#include <stdint.h>

// ---------------- problem constants ----------------
#define N_NODES   131072
#define G_GRAPHS  1024
#define NPG0      128
#define H_DIM     128
#define E_EDGES   2097152
#define EPG       2048
#define L_LAYERS  3
#define C_CLASSES 10
#define BN_EPS    1e-5f
#define INV_SQRT2 0.70710678118654752440f
#define N_SLOTS   10

// ---------------- scratch ----------------
__device__ float g_bufA[(size_t)N_NODES * H_DIM];
__device__ float g_bufB[(size_t)N_NODES * H_DIM];
__device__ float g_X[(size_t)(N_NODES / 2) * H_DIM];
__device__ float g_embraw[L_LAYERS * G_GRAPHS * H_DIM];
__device__ float g_statsAll[N_SLOTS * 256];
__device__ __nv_bfloat16 g_wimg[7 * 2 * 16384];   // [7 weights][hi|lo][K=128][N=128]

// ---------------- helpers ----------------
__device__ __forceinline__ uint32_t smem_u32(const void* p) {
    uint32_t a;
    asm("{ .reg .u64 t; cvta.to.shared.u64 t, %1; cvt.u32.u64 %0, t; }" : "=r"(a) : "l"(p));
    return a;
}
__device__ __forceinline__ uint32_t pack2(__nv_bfloat16 a, __nv_bfloat16 b) {
    __nv_bfloat162 t; t.x = a; t.y = b; return *(uint32_t*)&t;
}
#define LDSM_X4(r, a) \
    asm volatile("ldmatrix.sync.aligned.m8n8.x4.shared.b16 {%0,%1,%2,%3}, [%4];" \
        : "=r"((r)[0]), "=r"((r)[1]), "=r"((r)[2]), "=r"((r)[3]) : "r"(a))
#define LDSM_X4T(r, a) \
    asm volatile("ldmatrix.sync.aligned.m8n8.x4.trans.shared.b16 {%0,%1,%2,%3}, [%4];" \
        : "=r"((r)[0]), "=r"((r)[1]), "=r"((r)[2]), "=r"((r)[3]) : "r"(a))
#define MMA_BF16(d, a, b0, b1) \
    asm volatile("mma.sync.aligned.m16n8k16.row.col.f32.bf16.bf16.f32 " \
        "{%0,%1,%2,%3}, {%4,%5,%6,%7}, {%8,%9}, {%0,%1,%2,%3};" \
        : "+f"((d)[0]), "+f"((d)[1]), "+f"((d)[2]), "+f"((d)[3]) \
        : "r"((a)[0]), "r"((a)[1]), "r"((a)[2]), "r"((a)[3]), "r"(b0), "r"(b1))
#define CP_ASYNC16(saddr, gptr) \
    asm volatile("cp.async.cg.shared.global [%0], [%1], 16;" \
        :: "r"((uint32_t)(saddr)), "l"(gptr) : "memory")
#define CP_COMMIT()  asm volatile("cp.async.commit_group;" ::: "memory")
#define CP_WAIT0()   asm volatile("cp.async.wait_group 0;" ::: "memory")

#define BH_BYTES  144   // half-N B row stride (128B data + 16B pad)
#define SK_BYTES  272   // Abar row stride
#define AH_BYTES  144   // half-K A row stride (72 elems)

// ---- shared smem layout ----
#define SBH       0        // B half plane hi (18432) — fused phase2: Y half hi
#define SBL       18432    // B half plane lo (18432) — fused phase2: Y half lo
#define SA_HI     36864    // A half hi (18432) — fused phase2: cnt/Abar (34816)
#define SA_LO     55296    // A half lo (18432)
#define SO_BIAS   73728
#define SO_SCALE  74240
#define SO_SHIFT  74752
#define SO_STAT   75264    // per-CTA stats staging [sum128|sq128] (1024)
#define BIG_SMEM  76288    // x3 CTAs = 228.9 KB <= 233.5 KB/SM

// ---------------- weight bf16 split + stats zero ----------------
__global__ void transw_kernel(const float* __restrict__ w0, const float* __restrict__ w1,
                              const float* __restrict__ w2, __nv_bfloat16* __restrict__ img,
                              float* __restrict__ statsAll) {
    int b = blockIdx.x;
    if (b == 7) {
        for (int i = threadIdx.x; i < N_SLOTS * 256; i += blockDim.x) statsAll[i] = 0.f;
        return;
    }
    const float* W = (b == 0) ? w0 : ((b <= 3) ? w1 + (size_t)(b - 1) * 16384
                                               : w2 + (size_t)(b - 4) * 16384);
    __nv_bfloat16* hi = img + (size_t)b * 32768;
    __nv_bfloat16* lo = hi + 16384;
    for (int i = threadIdx.x; i < 16384; i += blockDim.x) {
        float v = W[i];
        __nv_bfloat16 h = __float2bfloat16(v);
        hi[i] = h;
        lo[i] = __float2bfloat16(v - __bfloat162float(h));
    }
}

// load A half-K (64 cols at kh*64) -> bf16 hi/lo split into SA planes
__device__ __forceinline__ void load_a_half(
    const char* smem, const float4* A4, int kh, int tid, int mode,
    const float* sscale, const float* sshift) {
    #pragma unroll
    for (int it = 0; it < 4; it++) {
        int i = tid + it * 256;            // 1024 groups of 8 floats
        int row = i >> 3, g = i & 7;
        float4 u = A4[row * 32 + kh * 16 + g * 2];
        float4 v = A4[row * 32 + kh * 16 + g * 2 + 1];
        float xv[8] = {u.x, u.y, u.z, u.w, v.x, v.y, v.z, v.w};
        if (mode) {
            int c0 = kh * 64 + g * 8;
            #pragma unroll
            for (int j = 0; j < 8; j++)
                xv[j] = fmaxf(fmaf(xv[j], sscale[c0 + j], sshift[c0 + j]), 0.f);
        }
        uint32_t hp[4], lp[4];
        #pragma unroll
        for (int j = 0; j < 4; j++) {
            __nv_bfloat16 h0 = __float2bfloat16(xv[2 * j]);
            __nv_bfloat16 h1 = __float2bfloat16(xv[2 * j + 1]);
            hp[j] = pack2(h0, h1);
            lp[j] = pack2(__float2bfloat16(xv[2 * j]     - __bfloat162float(h0)),
                          __float2bfloat16(xv[2 * j + 1] - __bfloat162float(h1)));
        }
        uint32_t off = (uint32_t)row * AH_BYTES + (uint32_t)g * 16;
        *(uint4*)(smem + SA_HI + off) = make_uint4(hp[0], hp[1], hp[2], hp[3]);
        *(uint4*)(smem + SA_LO + off) = make_uint4(lp[0], lp[1], lp[2], lp[3]);
    }
}

// 3-term MMA over one K half (half-N tile; acc[2][4][4])
__device__ __forceinline__ void mma_half(
    float acc[2][4][4], uint32_t sb, int kh, int wm, int wn, int lane) {
    const uint32_t aA = sb + SA_HI + (uint32_t)(wm * 32 + (lane & 15)) * AH_BYTES
                      + (uint32_t)(lane >> 4) * 16;
    const uint32_t aB = sb + SBH + (uint32_t)(lane & 15) * BH_BYTES
                      + (uint32_t)(wn * 64) + (uint32_t)(lane >> 4) * 16;
    #pragma unroll
    for (int ks = 0; ks < 4; ks++) {
        int kidx = kh * 4 + ks;
        uint32_t ah[2][4], al[2][4], bh[2][4], bl[2][4];
        #pragma unroll
        for (int mt = 0; mt < 2; mt++) {
            uint32_t ad = aA + (uint32_t)mt * (16 * AH_BYTES) + (uint32_t)ks * 32;
            LDSM_X4(ah[mt], ad);
            LDSM_X4(al[mt], ad + (SA_LO - SA_HI));
        }
        #pragma unroll
        for (int nt2 = 0; nt2 < 2; nt2++) {
            uint32_t bd = aB + (uint32_t)kidx * (16 * BH_BYTES) + (uint32_t)nt2 * 32;
            LDSM_X4T(bh[nt2], bd);
            LDSM_X4T(bl[nt2], bd + (SBL - SBH));
        }
        #pragma unroll
        for (int mt = 0; mt < 2; mt++)
            #pragma unroll
            for (int nt = 0; nt < 4; nt++) {
                uint32_t b0h = bh[nt >> 1][(nt & 1) * 2], b1h = bh[nt >> 1][(nt & 1) * 2 + 1];
                uint32_t b0l = bl[nt >> 1][(nt & 1) * 2], b1l = bl[nt >> 1][(nt & 1) * 2 + 1];
                MMA_BF16(acc[mt][nt], ah[mt], b0h, b1h);
                MMA_BF16(acc[mt][nt], ah[mt], b0l, b1l);
                MMA_BF16(acc[mt][nt], al[mt], b0h, b1h);
            }
    }
}

// epilogue: + bias, channel stats (smem-staged), fp32 store (cols nh*64..+63)
__device__ __forceinline__ void epilogue_f32(
    float acc[2][4][4], char* smem, float* Cb, float* statsOut,
    int wm, int wn, int lane, int tid, int nh) {
    const float* sbias = (float*)(smem + SO_BIAS);
    float* sstat = (float*)(smem + SO_STAT);
    float s[4][2], q[4][2];
    #pragma unroll
    for (int nt = 0; nt < 4; nt++) { s[nt][0] = s[nt][1] = q[nt][0] = q[nt][1] = 0.f; }
    const int cbase = nh * 64 + wn * 32 + (lane & 3) * 2;
    const int rbase = wm * 32 + (lane >> 2);
    #pragma unroll
    for (int mt = 0; mt < 2; mt++) {
        int r0 = rbase + mt * 16, r1 = r0 + 8;
        #pragma unroll
        for (int nt = 0; nt < 4; nt++) {
            int c = cbase + nt * 8;
            float b0 = sbias[c], b1 = sbias[c + 1];
            float y0 = acc[mt][nt][0] + b0, y1 = acc[mt][nt][1] + b1;
            float y2 = acc[mt][nt][2] + b0, y3 = acc[mt][nt][3] + b1;
            s[nt][0] += y0 + y2;           s[nt][1] += y1 + y3;
            q[nt][0] += y0 * y0 + y2 * y2; q[nt][1] += y1 * y1 + y3 * y3;
            *(float2*)(Cb + r0 * 128 + c) = make_float2(y0, y1);
            *(float2*)(Cb + r1 * 128 + c) = make_float2(y2, y3);
        }
    }
    #pragma unroll
    for (int off = 16; off >= 4; off >>= 1)
        #pragma unroll
        for (int nt = 0; nt < 4; nt++) {
            s[nt][0] += __shfl_down_sync(0xFFFFFFFFu, s[nt][0], off);
            s[nt][1] += __shfl_down_sync(0xFFFFFFFFu, s[nt][1], off);
            q[nt][0] += __shfl_down_sync(0xFFFFFFFFu, q[nt][0], off);
            q[nt][1] += __shfl_down_sync(0xFFFFFFFFu, q[nt][1], off);
        }
    if (lane < 4) {
        #pragma unroll
        for (int nt = 0; nt < 4; nt++) {
            int c = cbase + nt * 8;
            atomicAdd(&sstat[c & 127],           s[nt][0]);
            atomicAdd(&sstat[(c & 127) + 1],     s[nt][1]);
            atomicAdd(&sstat[128 + (c & 127)],     q[nt][0]);
            atomicAdd(&sstat[128 + (c & 127) + 1], q[nt][1]);
        }
    }
    __syncthreads();
    // sstat holds this CTA's contributions at local channel idx; map back with nh
    if (tid < 256) {
        int local = tid & 127;                // channel within [0,128)
        // only channels this CTA touched (nh*64..nh*64+63) are nonzero; add all (zeros ok)
        atomicAdd(&statsOut[(tid & 128) + local], sstat[tid]);
    }
}

// BN coef setup + zero smem stat staging, then sync
__device__ __forceinline__ void setup_coefs(
    char* smem, const float* bias, const float* bnG, const float* bnB,
    const float* statsIn, float nIn, int mode, int tid) {
    float* sbias  = (float*)(smem + SO_BIAS);
    float* sscale = (float*)(smem + SO_SCALE);
    float* sshift = (float*)(smem + SO_SHIFT);
    if (tid < 128) {
        sbias[tid] = bias[tid];
        if (mode) {
            float s = statsIn[tid], q = statsIn[128 + tid];
            float m = s / nIn, v = q / nIn - m * m;
            float sc = bnG[tid] * rsqrtf(v + BN_EPS);
            sscale[tid] = sc;
            sshift[tid] = fmaf(-m, sc, bnB[tid]);
        }
    }
    if (tid < 256) ((float*)(smem + SO_STAT))[tid] = 0.f;
    __syncthreads();
}

// half-N B planes (cols nh*64..nh*64+63) via cp.async
__device__ __forceinline__ void load_b_half_async(
    uint32_t sbm, const __nv_bfloat16* Wimg, int nh, int tid) {
    const uint4* bh = (const uint4*)Wimg;      // hi: 2048 uint4, lo follows
    #pragma unroll
    for (int it = 0; it < 4; it++) {
        int i = tid + it * 256;                // 1024 uint4 per plane
        int k = i >> 3, g = i & 7;
        int srci = k * 16 + nh * 8 + g;
        uint32_t off = (uint32_t)k * BH_BYTES + (uint32_t)g * 16;
        CP_ASYNC16(sbm + SBH + off, bh + srci);
        CP_ASYNC16(sbm + SBL + off, bh + 2048 + srci);
    }
    CP_COMMIT();
}

// ---------------- tc_gemm (half-N tiles, 3 CTA/SM, cp.async B) ----------------
__global__ __launch_bounds__(256, 3) void tc_gemm(
    const float* __restrict__ A, const __nv_bfloat16* __restrict__ Wimg,
    const float* __restrict__ bias,
    const float* __restrict__ bnG, const float* __restrict__ bnB,
    const float* __restrict__ statsIn, float nIn, int mode,
    float* __restrict__ Cf, float* __restrict__ statsOut) {
    extern __shared__ char smem[];
    const uint32_t sb = smem_u32(smem);
    const int tid = threadIdx.x, wid = tid >> 5, lane = tid & 31;
    const int wm = wid >> 1, wn = wid & 1;
    const int mb = blockIdx.x >> 1, nh = blockIdx.x & 1;

    setup_coefs(smem, bias, bnG, bnB, statsIn, nIn, mode, tid);
    load_b_half_async(sb, Wimg, nh, tid);      // in flight during A half-0 load

    const float4* A4 = (const float4*)(A + (size_t)mb * 16384);
    float* sscale = (float*)(smem + SO_SCALE);
    float* sshift = (float*)(smem + SO_SHIFT);

    float acc[2][4][4];
    #pragma unroll
    for (int mt = 0; mt < 2; mt++)
        #pragma unroll
        for (int nt = 0; nt < 4; nt++)
            #pragma unroll
            for (int j = 0; j < 4; j++) acc[mt][nt][j] = 0.f;

    load_a_half(smem, A4, 0, tid, mode, sscale, sshift);
    CP_WAIT0();
    __syncthreads();
    mma_half(acc, sb, 0, wm, wn, lane);
    __syncthreads();
    load_a_half(smem, A4, 1, tid, mode, sscale, sshift);
    __syncthreads();
    mma_half(acc, sb, 1, wm, wn, lane);
    __syncthreads();

    epilogue_f32(acc, smem, Cf + (size_t)mb * 16384, statsOut, wm, wn, lane, tid, nh);
}

// ---------------- fused layer (half-N): H_half = (I+A)(op(x)@W1)_half + b1 -----
__global__ __launch_bounds__(256, 3) void fused_layer(
    const float* __restrict__ A, const __nv_bfloat16* __restrict__ W1img,
    const int* __restrict__ src, const int* __restrict__ dst,
    const float* __restrict__ bias,
    const float* __restrict__ bnG, const float* __restrict__ bnB,
    const float* __restrict__ statsIn, float nIn, int mode,
    float* __restrict__ H, float* __restrict__ statsOut, int layer) {
    extern __shared__ char smem[];
    const uint32_t sb = smem_u32(smem);
    const int tid = threadIdx.x, wid = tid >> 5, lane = tid & 31;
    const int wm = wid >> 1, wn = wid & 1;
    const int mb = blockIdx.x >> 1, nh = blockIdx.x & 1;

    setup_coefs(smem, bias, bnG, bnB, statsIn, nIn, mode, tid);
    load_b_half_async(sb, W1img, nh, tid);

    const float4* A4 = (const float4*)(A + (size_t)mb * 16384);
    float* sscale = (float*)(smem + SO_SCALE);
    float* sshift = (float*)(smem + SO_SHIFT);

    float acc[2][4][4];
    #pragma unroll
    for (int mt = 0; mt < 2; mt++)
        #pragma unroll
        for (int nt = 0; nt < 4; nt++)
            #pragma unroll
            for (int j = 0; j < 4; j++) acc[mt][nt][j] = 0.f;

    load_a_half(smem, A4, 0, tid, mode, sscale, sshift);
    CP_WAIT0();
    __syncthreads();
    mma_half(acc, sb, 0, wm, wn, lane);
    __syncthreads();
    load_a_half(smem, A4, 1, tid, mode, sscale, sshift);
    __syncthreads();
    mma_half(acc, sb, 1, wm, wn, lane);
    __syncthreads();   // done with W1 half planes + A planes

    // Y half fragments -> bf16 hi/lo into SBH/SBL (local col 0..63); zero cnt region
    {
        const int cbase = wn * 32 + (lane & 3) * 2;
        const int rbase = wm * 32 + (lane >> 2);
        #pragma unroll
        for (int mt = 0; mt < 2; mt++) {
            int r0 = rbase + mt * 16, r1 = r0 + 8;
            #pragma unroll
            for (int nt = 0; nt < 4; nt++) {
                int c = cbase + nt * 8;
                float y0 = acc[mt][nt][0], y1 = acc[mt][nt][1];
                float y2 = acc[mt][nt][2], y3 = acc[mt][nt][3];
                __nv_bfloat16 h0 = __float2bfloat16(y0), h1 = __float2bfloat16(y1);
                __nv_bfloat16 h2 = __float2bfloat16(y2), h3 = __float2bfloat16(y3);
                *(uint32_t*)(smem + SBH + (uint32_t)r0 * BH_BYTES + (uint32_t)c * 2) = pack2(h0, h1);
                *(uint32_t*)(smem + SBH + (uint32_t)r1 * BH_BYTES + (uint32_t)c * 2) = pack2(h2, h3);
                *(uint32_t*)(smem + SBL + (uint32_t)r0 * BH_BYTES + (uint32_t)c * 2) =
                    pack2(__float2bfloat16(y0 - __bfloat162float(h0)),
                          __float2bfloat16(y1 - __bfloat162float(h1)));
                *(uint32_t*)(smem + SBL + (uint32_t)r1 * BH_BYTES + (uint32_t)c * 2) =
                    pack2(__float2bfloat16(y2 - __bfloat162float(h2)),
                          __float2bfloat16(y3 - __bfloat162float(h3)));
            }
        }
        uint4* az = (uint4*)(smem + SA_HI);   // cnt/Abar: 34816 B = 2176 uint4
        for (int i = tid; i < 2176; i += 256) az[i] = make_uint4(0, 0, 0, 0);
    }
    __syncthreads();

    // packed 16-bit pair counts via int atomics (rows of 68 words = 272 B)
    {
        int* cntw = (int*)(smem + SA_HI);
        const int gb = 1 << layer, npg = NPG0 >> layer;
        const int g0 = mb * gb;
        const int tot = gb * EPG;
        for (int idx = tid; idx < tot; idx += 256) {
            int j = idx >> 11;
            int e = (g0 + j) * EPG + (idx & 2047);
            int nb = (g0 + j) * NPG0;
            int d = (dst[e] - nb) >> layer;
            int s = (src[e] - nb) >> layer;
            int row = j * npg + d, col = j * npg + s;
            atomicAdd(&cntw[row * 68 + (col >> 1)], 1 << ((col & 1) * 16));
        }
    }
    __syncthreads();

    // counts -> bf16 Abar (+I), in place
    {
        uint32_t* cw = (uint32_t*)(smem + SA_HI);
        for (int i = tid; i < 128 * 64; i += 256) {
            int row = i >> 6, w = i & 63;
            int col = w * 2;
            uint32_t v = cw[row * 68 + w];
            float v0 = (float)(v & 0xFFFFu) + ((row == col)     ? 1.f : 0.f);
            float v1 = (float)(v >> 16)     + ((row == col + 1) ? 1.f : 0.f);
            cw[row * 68 + w] = pack2(__float2bfloat16(v0), __float2bfloat16(v1));
        }
    }
    __syncthreads();

    // agg MMA: acc2 = Abar @ (Yhi + Ylo) over the 64-col half
    float acc2[2][4][4];
    #pragma unroll
    for (int mt = 0; mt < 2; mt++)
        #pragma unroll
        for (int nt = 0; nt < 4; nt++)
            #pragma unroll
            for (int j = 0; j < 4; j++) acc2[mt][nt][j] = 0.f;
    {
        const uint32_t aA = sb + SA_HI + (uint32_t)(wm * 32 + (lane & 15)) * SK_BYTES
                          + (uint32_t)(lane >> 4) * 16;
        const uint32_t aB = sb + SBH + (uint32_t)(lane & 15) * BH_BYTES
                          + (uint32_t)(wn * 64) + (uint32_t)(lane >> 4) * 16;
        #pragma unroll
        for (int ks = 0; ks < 8; ks++) {
            uint32_t a[2][4], bh[2][4], bl[2][4];
            #pragma unroll
            for (int mt = 0; mt < 2; mt++)
                LDSM_X4(a[mt], aA + (uint32_t)mt * (16 * SK_BYTES) + (uint32_t)ks * 32);
            #pragma unroll
            for (int nt2 = 0; nt2 < 2; nt2++) {
                uint32_t bd = aB + (uint32_t)ks * (16 * BH_BYTES) + (uint32_t)nt2 * 32;
                LDSM_X4T(bh[nt2], bd);
                LDSM_X4T(bl[nt2], bd + (SBL - SBH));
            }
            #pragma unroll
            for (int mt = 0; mt < 2; mt++)
                #pragma unroll
                for (int nt = 0; nt < 4; nt++) {
                    uint32_t b0h = bh[nt >> 1][(nt & 1) * 2], b1h = bh[nt >> 1][(nt & 1) * 2 + 1];
                    uint32_t b0l = bl[nt >> 1][(nt & 1) * 2], b1l = bl[nt >> 1][(nt & 1) * 2 + 1];
                    MMA_BF16(acc2[mt][nt], a[mt], b0h, b1h);
                    MMA_BF16(acc2[mt][nt], a[mt], b0l, b1l);
                }
        }
    }
    __syncthreads();
    epilogue_f32(acc2, smem, H + (size_t)mb * 16384, statsOut, wm, wn, lane, tid, nh);
}

// ---------------- pool: inline BN+relu -> Haar -> graph sum + embd stats -------
__global__ __launch_bounds__(256) void pool_kernel(
    const float* __restrict__ Hin,
    const float* __restrict__ bnG, const float* __restrict__ bnB,
    const float* __restrict__ statsIn, float nIn,
    float* __restrict__ Xout, float* __restrict__ embraw,
    float* __restrict__ statsOut, int npg_in) {
    __shared__ float es[128], psc[128], psh[128];
    const int g = blockIdx.x, tid = threadIdx.x;
    if (tid < 128) {
        es[tid] = 0.f;
        float sv = statsIn[tid], qv = statsIn[128 + tid];
        float m = sv / nIn, v = qv / nIn - m * m;
        float c_ = bnG[tid] * rsqrtf(v + BN_EPS);
        psc[tid] = c_;
        psh[tid] = fmaf(-m, c_, bnB[tid]);
    }
    __syncthreads();

    const int npg_out = npg_in >> 1;
    const float4* in4 = (const float4*)(Hin + (size_t)g * npg_in * 128);
    float4* out4 = (float4*)(Xout + (size_t)g * npg_out * 128);

    for (int i = tid; i < npg_out * 32; i += 256) {
        int row = i >> 5, c4 = i & 31, c = c4 * 4;
        float4 a = in4[(2 * row) * 32 + c4];
        float4 b = in4[(2 * row + 1) * 32 + c4];
        float4 p;
        p.x = (fmaxf(fmaf(a.x, psc[c+0], psh[c+0]), 0.f) + fmaxf(fmaf(b.x, psc[c+0], psh[c+0]), 0.f)) * INV_SQRT2;
        p.y = (fmaxf(fmaf(a.y, psc[c+1], psh[c+1]), 0.f) + fmaxf(fmaf(b.y, psc[c+1], psh[c+1]), 0.f)) * INV_SQRT2;
        p.z = (fmaxf(fmaf(a.z, psc[c+2], psh[c+2]), 0.f) + fmaxf(fmaf(b.z, psc[c+2], psh[c+2]), 0.f)) * INV_SQRT2;
        p.w = (fmaxf(fmaf(a.w, psc[c+3], psh[c+3]), 0.f) + fmaxf(fmaf(b.w, psc[c+3], psh[c+3]), 0.f)) * INV_SQRT2;
        out4[i] = p;
        atomicAdd(&es[c + 0], p.x);
        atomicAdd(&es[c + 1], p.y);
        atomicAdd(&es[c + 2], p.z);
        atomicAdd(&es[c + 3], p.w);
    }
    __syncthreads();
    if (tid < 128) {
        float v = es[tid];
        embraw[g * 128 + tid] = v;
        atomicAdd(&statsOut[tid], v);
        atomicAdd(&statsOut[128 + tid], v * v);
    }
}

// ---------------- final linear with inline embedding-BN ------------------------
__global__ void final_linear_kernel(
    const float* __restrict__ embraw, const float* __restrict__ statsAll,
    const float* __restrict__ bneG, const float* __restrict__ bneB,
    const float* __restrict__ W, const float* __restrict__ b, float* __restrict__ out) {
    const int g = blockIdx.x, lane = threadIdx.x;
    float acc[C_CLASSES];
    #pragma unroll
    for (int c = 0; c < C_CLASSES; c++) acc[c] = 0.f;
    for (int k = lane; k < L_LAYERS * H_DIM; k += 32) {
        int layer = k >> 7, c = k & 127;
        const float* st = statsAll + (3 + 3 * layer) * 256;
        float m = st[c] / (float)G_GRAPHS;
        float v = st[128 + c] / (float)G_GRAPHS - m * m;
        float sc = bneG[layer * 128 + c] * rsqrtf(v + BN_EPS);
        float sh = fmaf(-m, sc, bneB[layer * 128 + c]);
        float e = fmaxf(fmaf(embraw[(size_t)layer * G_GRAPHS * 128 + g * 128 + c], sc, sh), 0.f);
        #pragma unroll
        for (int c10 = 0; c10 < C_CLASSES; c10++)
            acc[c10] = fmaf(e, W[k * C_CLASSES + c10], acc[c10]);
    }
    #pragma unroll
    for (int off = 16; off > 0; off >>= 1)
        #pragma unroll
        for (int c = 0; c < C_CLASSES; c++)
            acc[c] += __shfl_down_sync(0xFFFFFFFFu, acc[c], off);
    if (lane == 0) {
        #pragma unroll
        for (int c = 0; c < C_CLASSES; c++)
            out[g * C_CLASSES + c] = acc[c] + b[c];
    }
}

// ---------------- host orchestration ----------------
extern "C" void kernel_launch(void* const* d_in, const int* in_sizes, int n_in,
                              void* d_out, int out_size) {
    const float* x           = (const float*)d_in[0];
    const int*   ei          = (const int*)d_in[1];
    const int*   src         = ei;
    const int*   dst         = ei + E_EDGES;
    const float* lin_start_w = (const float*)d_in[2];
    const float* lin_start_b = (const float*)d_in[3];
    const float* bn_start_g  = (const float*)d_in[4];
    const float* bn_start_b  = (const float*)d_in[5];
    const float* conv_w1     = (const float*)d_in[6];
    const float* conv_b1     = (const float*)d_in[7];
    const float* conv_bn_g   = (const float*)d_in[8];
    const float* conv_bn_b   = (const float*)d_in[9];
    const float* conv_w2     = (const float*)d_in[10];
    const float* conv_b2     = (const float*)d_in[11];
    const float* bn_g        = (const float*)d_in[12];
    const float* bn_b        = (const float*)d_in[13];
    const float* bne_g       = (const float*)d_in[14];
    const float* bne_b       = (const float*)d_in[15];
    const float* lin_w       = (const float*)d_in[16];
    const float* lin_b       = (const float*)d_in[17];
    float* out = (float*)d_out;

    float *bufA, *bufB, *bufX, *embraw, *statsAll;
    __nv_bfloat16* wimg;
    cudaGetSymbolAddress((void**)&bufA,     g_bufA);
    cudaGetSymbolAddress((void**)&bufB,     g_bufB);
    cudaGetSymbolAddress((void**)&bufX,     g_X);
    cudaGetSymbolAddress((void**)&embraw,   g_embraw);
    cudaGetSymbolAddress((void**)&statsAll, g_statsAll);
    cudaGetSymbolAddress((void**)&wimg,     g_wimg);

    cudaFuncSetAttribute(tc_gemm, cudaFuncAttributeMaxDynamicSharedMemorySize, BIG_SMEM);
    cudaFuncSetAttribute(fused_layer, cudaFuncAttributeMaxDynamicSharedMemorySize, BIG_SMEM);

    transw_kernel<<<8, 256>>>(lin_start_w, conv_w1, conv_w2, wimg, statsAll);

    float* slot0 = statsAll;

    // Stage 0: bufB = x @ W_start + b  (stats slot0)
    // bufB (not bufA): with 2 CTAs per M-tile, fused layer-0 must NOT be in-place.
    tc_gemm<<<2 * (N_NODES / 128), 256, BIG_SMEM>>>(
        x, wimg, lin_start_b, nullptr, nullptr, nullptr, 0.f, 0, bufB, slot0);

    for (int i = 0; i < L_LAYERS; i++) {
        const int n = N_NODES >> i;
        const int npg = NPG0 >> i;
        float* slotH = statsAll + (1 + 3 * i) * 256;
        float* slotG = statsAll + (2 + 3 * i) * 256;
        float* slotE = statsAll + (3 + 3 * i) * 256;

        // fused: bufA = (I+A)(op(in)@W1) + b1   (in = bufB for layer0, bufX after)
        const float* ain = (i == 0) ? (const float*)bufB : (const float*)bufX;
        fused_layer<<<2 * (n / 128), 256, BIG_SMEM>>>(
            ain, wimg + (size_t)(1 + i) * 32768, src, dst, conv_b1 + i * H_DIM,
            (i == 0) ? bn_start_g : nullptr, (i == 0) ? bn_start_b : nullptr,
            (i == 0) ? slot0 : nullptr, (float)N_NODES, (i == 0) ? 1 : 0,
            bufA, slotH, i);

        // bufB = relu(bn(bufA)) @ W2 + b2  (stats slotG)
        tc_gemm<<<2 * (n / 128), 256, BIG_SMEM>>>(
            bufA, wimg + (size_t)(4 + i) * 32768, conv_b2 + i * H_DIM,
            conv_bn_g + i * H_DIM, conv_bn_b + i * H_DIM, slotH, (float)n, 1,
            bufB, slotG);

        // pool: bn(bufB)+relu -> Haar -> bufX; embd sums + stats slotE
        pool_kernel<<<G_GRAPHS, 256>>>(
            bufB, bn_g + i * H_DIM, bn_b + i * H_DIM, slotG, (float)n,
            bufX, embraw + (size_t)i * G_GRAPHS * H_DIM, slotE, npg);
    }

    final_linear_kernel<<<G_GRAPHS, 32>>>(
        embraw, statsAll, bne_g, bne_b, lin_w, lin_b, out);
}

// round 15
// speedup vs baseline: 1.1045x; 1.1045x over previous
#include <cuda_runtime.h>
#include <cuda_bf16.h>
#include <math.h>
#include <stdint.h>

// ---------------- problem constants ----------------
#define N_NODES   131072
#define G_GRAPHS  1024
#define NPG0      128
#define H_DIM     128
#define E_EDGES   2097152
#define EPG       2048
#define L_LAYERS  3
#define C_CLASSES 10
#define BN_EPS    1e-5f
#define INV_SQRT2 0.70710678118654752440f
#define N_SLOTS   10
#define XPLANE    ((size_t)(N_NODES / 2) * H_DIM)   // bf16 plane stride in g_X

// ---------------- scratch ----------------
__device__ float g_bufA[(size_t)N_NODES * H_DIM];
__device__ float g_bufB[(size_t)N_NODES * H_DIM];
__device__ float g_X[(size_t)(N_NODES / 2) * H_DIM];   // holds bf16 hi|lo planes
__device__ float g_embraw[L_LAYERS * G_GRAPHS * H_DIM];
__device__ float g_statsAll[N_SLOTS * 256];
__device__ __nv_bfloat16 g_wimg[7 * 2 * 16384];   // [7 weights][hi|lo][K=128][N=128]

// ---------------- helpers ----------------
__device__ __forceinline__ uint32_t smem_u32(const void* p) {
    uint32_t a;
    asm("{ .reg .u64 t; cvta.to.shared.u64 t, %1; cvt.u32.u64 %0, t; }" : "=r"(a) : "l"(p));
    return a;
}
__device__ __forceinline__ uint32_t pack2(__nv_bfloat16 a, __nv_bfloat16 b) {
    __nv_bfloat162 t; t.x = a; t.y = b; return *(uint32_t*)&t;
}
#define LDSM_X4(r, a) \
    asm volatile("ldmatrix.sync.aligned.m8n8.x4.shared.b16 {%0,%1,%2,%3}, [%4];" \
        : "=r"((r)[0]), "=r"((r)[1]), "=r"((r)[2]), "=r"((r)[3]) : "r"(a))
#define LDSM_X4T(r, a) \
    asm volatile("ldmatrix.sync.aligned.m8n8.x4.trans.shared.b16 {%0,%1,%2,%3}, [%4];" \
        : "=r"((r)[0]), "=r"((r)[1]), "=r"((r)[2]), "=r"((r)[3]) : "r"(a))
#define MMA_BF16(d, a, b0, b1) \
    asm volatile("mma.sync.aligned.m16n8k16.row.col.f32.bf16.bf16.f32 " \
        "{%0,%1,%2,%3}, {%4,%5,%6,%7}, {%8,%9}, {%0,%1,%2,%3};" \
        : "+f"((d)[0]), "+f"((d)[1]), "+f"((d)[2]), "+f"((d)[3]) \
        : "r"((a)[0]), "r"((a)[1]), "r"((a)[2]), "r"((a)[3]), "r"(b0), "r"(b1))
#define CP_ASYNC16(saddr, gptr) \
    asm volatile("cp.async.cg.shared.global [%0], [%1], 16;" \
        :: "r"((uint32_t)(saddr)), "l"(gptr) : "memory")
#define CP_COMMIT()  asm volatile("cp.async.commit_group;" ::: "memory")
#define CP_WAIT0()   asm volatile("cp.async.wait_group 0;" ::: "memory")

#define SK_BYTES  272   // full-K bf16 row stride (136 elems)
#define AH_BYTES  144   // half-K bf16 row stride (72 elems)

// ---- shared smem layout (both big kernels) ----
#define SB_HI     0        // full B plane hi (34816) — in fused: W1 hi, later Y hi
#define SB_LO     34816    // full B plane lo          — in fused: W1 lo, later Y lo
#define SA_HI     69632    // A half hi (18432) — in fused phase2: cnt/Abar (34816)
#define SA_LO     88064    // A half lo (18432)
#define SO_BIAS   106496
#define SO_SCALE  107008
#define SO_SHIFT  107520
#define SO_STAT   108032   // per-CTA stats staging [sum128|sq128] (1024)
#define BIG_SMEM  109056

// ---------------- weight bf16 split + stats zero ----------------
__global__ void transw_kernel(const float* __restrict__ w0, const float* __restrict__ w1,
                              const float* __restrict__ w2, __nv_bfloat16* __restrict__ img,
                              float* __restrict__ statsAll) {
    int b = blockIdx.x;
    if (b == 7) {
        for (int i = threadIdx.x; i < N_SLOTS * 256; i += blockDim.x) statsAll[i] = 0.f;
        return;
    }
    const float* W = (b == 0) ? w0 : ((b <= 3) ? w1 + (size_t)(b - 1) * 16384
                                               : w2 + (size_t)(b - 4) * 16384);
    __nv_bfloat16* hi = img + (size_t)b * 32768;
    __nv_bfloat16* lo = hi + 16384;
    for (int i = threadIdx.x; i < 16384; i += blockDim.x) {
        float v = W[i];
        __nv_bfloat16 h = __float2bfloat16(v);
        hi[i] = h;
        lo[i] = __float2bfloat16(v - __bfloat162float(h));
    }
}

// load A half-K (64 cols at kh*64) from fp32 -> bf16 hi/lo split into SA planes
__device__ __forceinline__ void load_a_half(
    const char* smem, const float4* A4, int kh, int tid, int mode,
    const float* sscale, const float* sshift) {
    #pragma unroll
    for (int it = 0; it < 4; it++) {
        int i = tid + it * 256;            // 1024 groups of 8 floats
        int row = i >> 3, g = i & 7;
        float4 u = A4[row * 32 + kh * 16 + g * 2];
        float4 v = A4[row * 32 + kh * 16 + g * 2 + 1];
        float xv[8] = {u.x, u.y, u.z, u.w, v.x, v.y, v.z, v.w};
        if (mode) {
            int c0 = kh * 64 + g * 8;
            #pragma unroll
            for (int j = 0; j < 8; j++)
                xv[j] = fmaxf(fmaf(xv[j], sscale[c0 + j], sshift[c0 + j]), 0.f);
        }
        uint32_t hp[4], lp[4];
        #pragma unroll
        for (int j = 0; j < 4; j++) {
            __nv_bfloat16 h0 = __float2bfloat16(xv[2 * j]);
            __nv_bfloat16 h1 = __float2bfloat16(xv[2 * j + 1]);
            hp[j] = pack2(h0, h1);
            lp[j] = pack2(__float2bfloat16(xv[2 * j]     - __bfloat162float(h0)),
                          __float2bfloat16(xv[2 * j + 1] - __bfloat162float(h1)));
        }
        uint32_t off = (uint32_t)row * AH_BYTES + (uint32_t)g * 16;
        *(uint4*)(smem + SA_HI + off) = make_uint4(hp[0], hp[1], hp[2], hp[3]);
        *(uint4*)(smem + SA_LO + off) = make_uint4(lp[0], lp[1], lp[2], lp[3]);
    }
}

// load A half-K from pre-split bf16 planes: pure uint4 copy (no convert)
__device__ __forceinline__ void load_a_half_copy(
    const char* smem, const uint4* Hi4, const uint4* Lo4, int kh, int tid) {
    #pragma unroll
    for (int it = 0; it < 4; it++) {
        int i = tid + it * 256;
        int row = i >> 3, g = i & 7;
        int srci = row * 16 + kh * 8 + g;      // plane row = 16 uint4 (256 B)
        uint32_t off = (uint32_t)row * AH_BYTES + (uint32_t)g * 16;
        *(uint4*)(smem + SA_HI + off) = Hi4[srci];
        *(uint4*)(smem + SA_LO + off) = Lo4[srci];
    }
}

// 3-term MMA over one K half (local ks 0..3, global kidx = kh*4+ks)
__device__ __forceinline__ void mma_half(
    float acc[2][8][4], uint32_t sb, int kh, int wm, int wn, int lane) {
    const uint32_t aA = sb + SA_HI + (uint32_t)(wm * 32 + (lane & 15)) * AH_BYTES
                      + (uint32_t)(lane >> 4) * 16;
    const uint32_t aB = sb + SB_HI + (uint32_t)(lane & 15) * SK_BYTES
                      + (uint32_t)(wn * 128) + (uint32_t)(lane >> 4) * 16;
    #pragma unroll
    for (int ks = 0; ks < 4; ks++) {
        int kidx = kh * 4 + ks;
        uint32_t ah[2][4], al[2][4], bh[4][4], bl[4][4];
        #pragma unroll
        for (int mt = 0; mt < 2; mt++) {
            uint32_t ad = aA + (uint32_t)mt * (16 * AH_BYTES) + (uint32_t)ks * 32;
            LDSM_X4(ah[mt], ad);
            LDSM_X4(al[mt], ad + (SA_LO - SA_HI));
        }
        #pragma unroll
        for (int nt2 = 0; nt2 < 4; nt2++) {
            uint32_t bd = aB + (uint32_t)kidx * (16 * SK_BYTES) + (uint32_t)nt2 * 32;
            LDSM_X4T(bh[nt2], bd);
            LDSM_X4T(bl[nt2], bd + (SB_LO - SB_HI));
        }
        #pragma unroll
        for (int mt = 0; mt < 2; mt++)
            #pragma unroll
            for (int nt = 0; nt < 8; nt++) {
                uint32_t b0h = bh[nt >> 1][(nt & 1) * 2], b1h = bh[nt >> 1][(nt & 1) * 2 + 1];
                uint32_t b0l = bl[nt >> 1][(nt & 1) * 2], b1l = bl[nt >> 1][(nt & 1) * 2 + 1];
                MMA_BF16(acc[mt][nt], ah[mt], b0h, b1h);
                MMA_BF16(acc[mt][nt], ah[mt], b0l, b1l);
                MMA_BF16(acc[mt][nt], al[mt], b0h, b1h);
            }
    }
}

// epilogue: + bias, channel stats (smem-staged), fp32 store
__device__ __forceinline__ void epilogue_f32(
    float acc[2][8][4], char* smem, float* Cb, float* statsOut,
    int wm, int wn, int lane, int tid) {
    const float* sbias = (float*)(smem + SO_BIAS);
    float* sstat = (float*)(smem + SO_STAT);
    float s[8][2], q[8][2];
    #pragma unroll
    for (int nt = 0; nt < 8; nt++) { s[nt][0] = s[nt][1] = q[nt][0] = q[nt][1] = 0.f; }
    const int cbase = wn * 64 + (lane & 3) * 2;
    const int rbase = wm * 32 + (lane >> 2);
    #pragma unroll
    for (int mt = 0; mt < 2; mt++) {
        int r0 = rbase + mt * 16, r1 = r0 + 8;
        #pragma unroll
        for (int nt = 0; nt < 8; nt++) {
            int c = cbase + nt * 8;
            float b0 = sbias[c], b1 = sbias[c + 1];
            float y0 = acc[mt][nt][0] + b0, y1 = acc[mt][nt][1] + b1;
            float y2 = acc[mt][nt][2] + b0, y3 = acc[mt][nt][3] + b1;
            s[nt][0] += y0 + y2;           s[nt][1] += y1 + y3;
            q[nt][0] += y0 * y0 + y2 * y2; q[nt][1] += y1 * y1 + y3 * y3;
            *(float2*)(Cb + r0 * 128 + c) = make_float2(y0, y1);
            *(float2*)(Cb + r1 * 128 + c) = make_float2(y2, y3);
        }
    }
    #pragma unroll
    for (int off = 16; off >= 4; off >>= 1)
        #pragma unroll
        for (int nt = 0; nt < 8; nt++) {
            s[nt][0] += __shfl_down_sync(0xFFFFFFFFu, s[nt][0], off);
            s[nt][1] += __shfl_down_sync(0xFFFFFFFFu, s[nt][1], off);
            q[nt][0] += __shfl_down_sync(0xFFFFFFFFu, q[nt][0], off);
            q[nt][1] += __shfl_down_sync(0xFFFFFFFFu, q[nt][1], off);
        }
    if (lane < 4) {
        #pragma unroll
        for (int nt = 0; nt < 8; nt++) {
            int c = cbase + nt * 8;
            atomicAdd(&sstat[c],           s[nt][0]);
            atomicAdd(&sstat[c + 1],       s[nt][1]);
            atomicAdd(&sstat[128 + c],     q[nt][0]);
            atomicAdd(&sstat[128 + c + 1], q[nt][1]);
        }
    }
    __syncthreads();
    if (tid < 256) atomicAdd(&statsOut[tid], sstat[tid]);
}

// BN coef setup + zero smem stat staging, then sync
__device__ __forceinline__ void setup_coefs(
    char* smem, const float* bias, const float* bnG, const float* bnB,
    const float* statsIn, float nIn, int mode, int tid) {
    float* sbias  = (float*)(smem + SO_BIAS);
    float* sscale = (float*)(smem + SO_SCALE);
    float* sshift = (float*)(smem + SO_SHIFT);
    if (tid < 128) {
        sbias[tid] = bias[tid];
        if (mode) {
            float s = statsIn[tid], q = statsIn[128 + tid];
            float m = s / nIn, v = q / nIn - m * m;
            float sc = bnG[tid] * rsqrtf(v + BN_EPS);
            sscale[tid] = sc;
            sshift[tid] = fmaf(-m, sc, bnB[tid]);
        }
    }
    if (tid < 256) ((float*)(smem + SO_STAT))[tid] = 0.f;
    __syncthreads();
}

// full B planes via cp.async (overlaps with subsequent A load phase)
__device__ __forceinline__ void load_b_planes_async(
    uint32_t sbm, const __nv_bfloat16* Wimg, int tid) {
    const uint4* bh = (const uint4*)Wimg;
    #pragma unroll
    for (int it = 0; it < 8; it++) {
        int i = tid + it * 256;
        int k = i >> 4, g = i & 15;
        uint32_t off = (uint32_t)k * SK_BYTES + (uint32_t)g * 16;
        CP_ASYNC16(sbm + SB_HI + off, bh + i);
        CP_ASYNC16(sbm + SB_LO + off, bh + 2048 + i);
    }
    CP_COMMIT();
}

// ---------------- tc_gemm: C = op(A) @ W + bias, + stats (K-split, 2 CTA/SM) ---
__global__ __launch_bounds__(256, 2) void tc_gemm(
    const float* __restrict__ A, const __nv_bfloat16* __restrict__ Wimg,
    const float* __restrict__ bias,
    const float* __restrict__ bnG, const float* __restrict__ bnB,
    const float* __restrict__ statsIn, float nIn, int mode,
    float* __restrict__ Cf, float* __restrict__ statsOut) {
    extern __shared__ char smem[];
    const uint32_t sb = smem_u32(smem);
    const int tid = threadIdx.x, wid = tid >> 5, lane = tid & 31;
    const int wm = wid >> 1, wn = wid & 1;

    setup_coefs(smem, bias, bnG, bnB, statsIn, nIn, mode, tid);
    load_b_planes_async(sb, Wimg, tid);          // in flight during A half-0 load

    const float4* A4 = (const float4*)(A + (size_t)blockIdx.x * 16384);
    float* sscale = (float*)(smem + SO_SCALE);
    float* sshift = (float*)(smem + SO_SHIFT);

    float acc[2][8][4];
    #pragma unroll
    for (int mt = 0; mt < 2; mt++)
        #pragma unroll
        for (int nt = 0; nt < 8; nt++)
            #pragma unroll
            for (int j = 0; j < 4; j++) acc[mt][nt][j] = 0.f;

    load_a_half(smem, A4, 0, tid, mode, sscale, sshift);
    CP_WAIT0();
    __syncthreads();
    mma_half(acc, sb, 0, wm, wn, lane);
    __syncthreads();
    load_a_half(smem, A4, 1, tid, mode, sscale, sshift);
    __syncthreads();
    mma_half(acc, sb, 1, wm, wn, lane);
    __syncthreads();

    epilogue_f32(acc, smem, Cf + (size_t)blockIdx.x * 16384, statsOut, wm, wn, lane, tid);
}

// ---------------- fused layer: H = (I+A)(op(x)@W1) + b1, + stats ----------------
// afmt 0: A fp32 (with optional BN via mode). afmt 2: A pre-split bf16 planes.
__global__ __launch_bounds__(256, 2) void fused_layer(
    const float* __restrict__ A,
    const __nv_bfloat16* __restrict__ Ahi, const __nv_bfloat16* __restrict__ Alo,
    const __nv_bfloat16* __restrict__ W1img,
    const int* __restrict__ src, const int* __restrict__ dst,
    const float* __restrict__ bias,
    const float* __restrict__ bnG, const float* __restrict__ bnB,
    const float* __restrict__ statsIn, float nIn, int afmt, int mode,
    float* __restrict__ H, float* __restrict__ statsOut, int layer) {
    extern __shared__ char smem[];
    const uint32_t sb = smem_u32(smem);
    const int tid = threadIdx.x, wid = tid >> 5, lane = tid & 31;
    const int wm = wid >> 1, wn = wid & 1;

    setup_coefs(smem, bias, bnG, bnB, statsIn, nIn, mode, tid);
    load_b_planes_async(sb, W1img, tid);

    const float4* A4 = (const float4*)(A + (size_t)blockIdx.x * 16384);
    const uint4* Hi4 = (const uint4*)(Ahi + (size_t)blockIdx.x * 16384);
    const uint4* Lo4 = (const uint4*)(Alo + (size_t)blockIdx.x * 16384);
    float* sscale = (float*)(smem + SO_SCALE);
    float* sshift = (float*)(smem + SO_SHIFT);

    float acc[2][8][4];
    #pragma unroll
    for (int mt = 0; mt < 2; mt++)
        #pragma unroll
        for (int nt = 0; nt < 8; nt++)
            #pragma unroll
            for (int j = 0; j < 4; j++) acc[mt][nt][j] = 0.f;

    if (afmt == 0) load_a_half(smem, A4, 0, tid, mode, sscale, sshift);
    else           load_a_half_copy(smem, Hi4, Lo4, 0, tid);
    CP_WAIT0();
    __syncthreads();
    mma_half(acc, sb, 0, wm, wn, lane);
    __syncthreads();
    if (afmt == 0) load_a_half(smem, A4, 1, tid, mode, sscale, sshift);
    else           load_a_half_copy(smem, Hi4, Lo4, 1, tid);
    __syncthreads();
    mma_half(acc, sb, 1, wm, wn, lane);
    __syncthreads();   // all warps done reading W1 + A planes

    // Y fragments -> bf16 hi/lo planes in smem (overwrite W1 planes); zero cnt region
    {
        const int cbase = wn * 64 + (lane & 3) * 2;
        const int rbase = wm * 32 + (lane >> 2);
        #pragma unroll
        for (int mt = 0; mt < 2; mt++) {
            int r0 = rbase + mt * 16, r1 = r0 + 8;
            #pragma unroll
            for (int nt = 0; nt < 8; nt++) {
                int c = cbase + nt * 8;
                float y0 = acc[mt][nt][0], y1 = acc[mt][nt][1];
                float y2 = acc[mt][nt][2], y3 = acc[mt][nt][3];
                __nv_bfloat16 h0 = __float2bfloat16(y0), h1 = __float2bfloat16(y1);
                __nv_bfloat16 h2 = __float2bfloat16(y2), h3 = __float2bfloat16(y3);
                *(uint32_t*)(smem + SB_HI + (uint32_t)r0 * SK_BYTES + (uint32_t)c * 2) = pack2(h0, h1);
                *(uint32_t*)(smem + SB_HI + (uint32_t)r1 * SK_BYTES + (uint32_t)c * 2) = pack2(h2, h3);
                *(uint32_t*)(smem + SB_LO + (uint32_t)r0 * SK_BYTES + (uint32_t)c * 2) =
                    pack2(__float2bfloat16(y0 - __bfloat162float(h0)),
                          __float2bfloat16(y1 - __bfloat162float(h1)));
                *(uint32_t*)(smem + SB_LO + (uint32_t)r1 * SK_BYTES + (uint32_t)c * 2) =
                    pack2(__float2bfloat16(y2 - __bfloat162float(h2)),
                          __float2bfloat16(y3 - __bfloat162float(h3)));
            }
        }
        uint4* az = (uint4*)(smem + SA_HI);
        for (int i = tid; i < 2176; i += 256) az[i] = make_uint4(0, 0, 0, 0);
    }
    __syncthreads();

    // packed 16-bit pair counts via int atomics (rows of 68 words = 272 B)
    {
        int* cntw = (int*)(smem + SA_HI);
        const int gb = 1 << layer, npg = NPG0 >> layer;
        const int g0 = blockIdx.x * gb;
        const int tot = gb * EPG;
        for (int idx = tid; idx < tot; idx += 256) {
            int j = idx >> 11;
            int e = (g0 + j) * EPG + (idx & 2047);
            int nb = (g0 + j) * NPG0;
            int d = (dst[e] - nb) >> layer;
            int s = (src[e] - nb) >> layer;
            int row = j * npg + d, col = j * npg + s;
            atomicAdd(&cntw[row * 68 + (col >> 1)], 1 << ((col & 1) * 16));
        }
    }
    __syncthreads();

    // counts -> bf16 Abar (+I), in place
    {
        uint32_t* cw = (uint32_t*)(smem + SA_HI);
        for (int i = tid; i < 128 * 64; i += 256) {
            int row = i >> 6, w = i & 63;
            int col = w * 2;
            uint32_t v = cw[row * 68 + w];
            float v0 = (float)(v & 0xFFFFu) + ((row == col)     ? 1.f : 0.f);
            float v1 = (float)(v >> 16)     + ((row == col + 1) ? 1.f : 0.f);
            cw[row * 68 + w] = pack2(__float2bfloat16(v0), __float2bfloat16(v1));
        }
    }
    __syncthreads();

    // agg MMA: acc2 = Abar @ (Yhi + Ylo)
    float acc2[2][8][4];
    #pragma unroll
    for (int mt = 0; mt < 2; mt++)
        #pragma unroll
        for (int nt = 0; nt < 8; nt++)
            #pragma unroll
            for (int j = 0; j < 4; j++) acc2[mt][nt][j] = 0.f;
    {
        const uint32_t aA = sb + SA_HI + (uint32_t)(wm * 32 + (lane & 15)) * SK_BYTES
                          + (uint32_t)(lane >> 4) * 16;
        const uint32_t aB = sb + SB_HI + (uint32_t)(lane & 15) * SK_BYTES
                          + (uint32_t)(wn * 128) + (uint32_t)(lane >> 4) * 16;
        #pragma unroll
        for (int ks = 0; ks < 8; ks++) {
            uint32_t a[2][4], bh[4][4], bl[4][4];
            #pragma unroll
            for (int mt = 0; mt < 2; mt++)
                LDSM_X4(a[mt], aA + (uint32_t)mt * (16 * SK_BYTES) + (uint32_t)ks * 32);
            #pragma unroll
            for (int nt2 = 0; nt2 < 4; nt2++) {
                uint32_t bd = aB + (uint32_t)ks * (16 * SK_BYTES) + (uint32_t)nt2 * 32;
                LDSM_X4T(bh[nt2], bd);
                LDSM_X4T(bl[nt2], bd + (SB_LO - SB_HI));
            }
            #pragma unroll
            for (int mt = 0; mt < 2; mt++)
                #pragma unroll
                for (int nt = 0; nt < 8; nt++) {
                    uint32_t b0h = bh[nt >> 1][(nt & 1) * 2], b1h = bh[nt >> 1][(nt & 1) * 2 + 1];
                    uint32_t b0l = bl[nt >> 1][(nt & 1) * 2], b1l = bl[nt >> 1][(nt & 1) * 2 + 1];
                    MMA_BF16(acc2[mt][nt], a[mt], b0h, b1h);
                    MMA_BF16(acc2[mt][nt], a[mt], b0l, b1l);
                }
        }
    }
    __syncthreads();
    epilogue_f32(acc2, smem, H + (size_t)blockIdx.x * 16384, statsOut, wm, wn, lane, tid);
}

// ---------------- pool: inline BN+relu -> Haar -> plane out + embd sums/stats --
__global__ __launch_bounds__(256) void pool_kernel(
    const float* __restrict__ Hin,
    const float* __restrict__ bnG, const float* __restrict__ bnB,
    const float* __restrict__ statsIn, float nIn,
    __nv_bfloat16* __restrict__ Xhi, __nv_bfloat16* __restrict__ Xlo, int writeX,
    float* __restrict__ embraw, float* __restrict__ statsOut, int npg_in) {
    __shared__ float es[128], psc[128], psh[128];
    const int g = blockIdx.x, tid = threadIdx.x;
    if (tid < 128) {
        es[tid] = 0.f;
        float sv = statsIn[tid], qv = statsIn[128 + tid];
        float m = sv / nIn, v = qv / nIn - m * m;
        float c_ = bnG[tid] * rsqrtf(v + BN_EPS);
        psc[tid] = c_;
        psh[tid] = fmaf(-m, c_, bnB[tid]);
    }
    __syncthreads();

    const int npg_out = npg_in >> 1;
    const float4* in4 = (const float4*)(Hin + (size_t)g * npg_in * 128);
    const size_t xbase = (size_t)g * npg_out * 128;

    // register accumulation: this thread's channels are fixed (c = (tid&31)*4)
    const int cfix = (tid & 31) * 4;
    float a0 = 0.f, a1 = 0.f, a2 = 0.f, a3 = 0.f;

    for (int i = tid; i < npg_out * 32; i += 256) {
        int row = i >> 5, c = cfix;
        float4 a = in4[(2 * row) * 32 + (i & 31)];
        float4 b = in4[(2 * row + 1) * 32 + (i & 31)];
        float4 p;
        p.x = (fmaxf(fmaf(a.x, psc[c+0], psh[c+0]), 0.f) + fmaxf(fmaf(b.x, psc[c+0], psh[c+0]), 0.f)) * INV_SQRT2;
        p.y = (fmaxf(fmaf(a.y, psc[c+1], psh[c+1]), 0.f) + fmaxf(fmaf(b.y, psc[c+1], psh[c+1]), 0.f)) * INV_SQRT2;
        p.z = (fmaxf(fmaf(a.z, psc[c+2], psh[c+2]), 0.f) + fmaxf(fmaf(b.z, psc[c+2], psh[c+2]), 0.f)) * INV_SQRT2;
        p.w = (fmaxf(fmaf(a.w, psc[c+3], psh[c+3]), 0.f) + fmaxf(fmaf(b.w, psc[c+3], psh[c+3]), 0.f)) * INV_SQRT2;
        if (writeX) {
            // split to hi/lo bf16 planes (captures fp32 to 2^-18; consumer copies verbatim)
            __nv_bfloat16 hx = __float2bfloat16(p.x), hy = __float2bfloat16(p.y);
            __nv_bfloat16 hz = __float2bfloat16(p.z), hw = __float2bfloat16(p.w);
            size_t e = xbase + (size_t)row * 128 + c;
            *(uint32_t*)(Xhi + e)     = pack2(hx, hy);
            *(uint32_t*)(Xhi + e + 2) = pack2(hz, hw);
            *(uint32_t*)(Xlo + e)     = pack2(__float2bfloat16(p.x - __bfloat162float(hx)),
                                              __float2bfloat16(p.y - __bfloat162float(hy)));
            *(uint32_t*)(Xlo + e + 2) = pack2(__float2bfloat16(p.z - __bfloat162float(hz)),
                                              __float2bfloat16(p.w - __bfloat162float(hw)));
        }
        a0 += p.x; a1 += p.y; a2 += p.z; a3 += p.w;
    }
    atomicAdd(&es[cfix + 0], a0);
    atomicAdd(&es[cfix + 1], a1);
    atomicAdd(&es[cfix + 2], a2);
    atomicAdd(&es[cfix + 3], a3);
    __syncthreads();
    if (tid < 128) {
        float v = es[tid];
        embraw[g * 128 + tid] = v;
        atomicAdd(&statsOut[tid], v);
        atomicAdd(&statsOut[128 + tid], v * v);
    }
}

// ---------------- final linear with inline embedding-BN ------------------------
__global__ void final_linear_kernel(
    const float* __restrict__ embraw, const float* __restrict__ statsAll,
    const float* __restrict__ bneG, const float* __restrict__ bneB,
    const float* __restrict__ W, const float* __restrict__ b, float* __restrict__ out) {
    const int g = blockIdx.x, lane = threadIdx.x;
    float acc[C_CLASSES];
    #pragma unroll
    for (int c = 0; c < C_CLASSES; c++) acc[c] = 0.f;
    for (int k = lane; k < L_LAYERS * H_DIM; k += 32) {
        int layer = k >> 7, c = k & 127;
        const float* st = statsAll + (3 + 3 * layer) * 256;
        float m = st[c] / (float)G_GRAPHS;
        float v = st[128 + c] / (float)G_GRAPHS - m * m;
        float sc = bneG[layer * 128 + c] * rsqrtf(v + BN_EPS);
        float sh = fmaf(-m, sc, bneB[layer * 128 + c]);
        float e = fmaxf(fmaf(embraw[(size_t)layer * G_GRAPHS * 128 + g * 128 + c], sc, sh), 0.f);
        #pragma unroll
        for (int c10 = 0; c10 < C_CLASSES; c10++)
            acc[c10] = fmaf(e, W[k * C_CLASSES + c10], acc[c10]);
    }
    #pragma unroll
    for (int off = 16; off > 0; off >>= 1)
        #pragma unroll
        for (int c = 0; c < C_CLASSES; c++)
            acc[c] += __shfl_down_sync(0xFFFFFFFFu, acc[c], off);
    if (lane == 0) {
        #pragma unroll
        for (int c = 0; c < C_CLASSES; c++)
            out[g * C_CLASSES + c] = acc[c] + b[c];
    }
}

// ---------------- host orchestration ----------------
extern "C" void kernel_launch(void* const* d_in, const int* in_sizes, int n_in,
                              void* d_out, int out_size) {
    const float* x           = (const float*)d_in[0];
    const int*   ei          = (const int*)d_in[1];
    const int*   src         = ei;
    const int*   dst         = ei + E_EDGES;
    const float* lin_start_w = (const float*)d_in[2];
    const float* lin_start_b = (const float*)d_in[3];
    const float* bn_start_g  = (const float*)d_in[4];
    const float* bn_start_b  = (const float*)d_in[5];
    const float* conv_w1     = (const float*)d_in[6];
    const float* conv_b1     = (const float*)d_in[7];
    const float* conv_bn_g   = (const float*)d_in[8];
    const float* conv_bn_b   = (const float*)d_in[9];
    const float* conv_w2     = (const float*)d_in[10];
    const float* conv_b2     = (const float*)d_in[11];
    const float* bn_g        = (const float*)d_in[12];
    const float* bn_b        = (const float*)d_in[13];
    const float* bne_g       = (const float*)d_in[14];
    const float* bne_b       = (const float*)d_in[15];
    const float* lin_w       = (const float*)d_in[16];
    const float* lin_b       = (const float*)d_in[17];
    float* out = (float*)d_out;

    float *bufA, *bufB, *bufX, *embraw, *statsAll;
    __nv_bfloat16* wimg;
    cudaGetSymbolAddress((void**)&bufA,     g_bufA);
    cudaGetSymbolAddress((void**)&bufB,     g_bufB);
    cudaGetSymbolAddress((void**)&bufX,     g_X);
    cudaGetSymbolAddress((void**)&embraw,   g_embraw);
    cudaGetSymbolAddress((void**)&statsAll, g_statsAll);
    cudaGetSymbolAddress((void**)&wimg,     g_wimg);

    __nv_bfloat16* Xhi = (__nv_bfloat16*)bufX;
    __nv_bfloat16* Xlo = Xhi + XPLANE;

    cudaFuncSetAttribute(tc_gemm, cudaFuncAttributeMaxDynamicSharedMemorySize, BIG_SMEM);
    cudaFuncSetAttribute(fused_layer, cudaFuncAttributeMaxDynamicSharedMemorySize, BIG_SMEM);

    transw_kernel<<<8, 256>>>(lin_start_w, conv_w1, conv_w2, wimg, statsAll);

    float* slot0 = statsAll;

    // Stage 0: bufA = x @ W_start + b  (stats slot0)
    tc_gemm<<<N_NODES / 128, 256, BIG_SMEM>>>(
        x, wimg, lin_start_b, nullptr, nullptr, nullptr, 0.f, 0, bufA, slot0);

    for (int i = 0; i < L_LAYERS; i++) {
        const int n = N_NODES >> i;
        const int npg = NPG0 >> i;
        float* slotH = statsAll + (1 + 3 * i) * 256;
        float* slotG = statsAll + (2 + 3 * i) * 256;
        float* slotE = statsAll + (3 + 3 * i) * 256;

        // fused: H = (I+A)(op(x)@W1) + b1
        // layer0: afmt=0 fp32 bufA (in-place safe: ONE CTA per tile), mode=1
        // layers>=1: afmt=2 bf16 planes from pool
        fused_layer<<<n / 128, 256, BIG_SMEM>>>(
            (i == 0) ? (const float*)bufA : nullptr,
            (i == 0) ? nullptr : Xhi, (i == 0) ? nullptr : Xlo,
            wimg + (size_t)(1 + i) * 32768, src, dst, conv_b1 + i * H_DIM,
            (i == 0) ? bn_start_g : nullptr, (i == 0) ? bn_start_b : nullptr,
            (i == 0) ? slot0 : nullptr, (float)N_NODES,
            (i == 0) ? 0 : 2, (i == 0) ? 1 : 0,
            bufA, slotH, i);

        // G = relu(bn(H)) @ W2 + b2   (stats slotG)
        tc_gemm<<<n / 128, 256, BIG_SMEM>>>(
            bufA, wimg + (size_t)(4 + i) * 32768, conv_b2 + i * H_DIM,
            conv_bn_g + i * H_DIM, conv_bn_b + i * H_DIM, slotH, (float)n, 1,
            bufB, slotG);

        // pool: bn(G)+relu -> Haar -> X planes (skip write on last layer);
        // embd sums + stats slotE
        pool_kernel<<<G_GRAPHS, 256>>>(
            bufB, bn_g + i * H_DIM, bn_b + i * H_DIM, slotG, (float)n,
            Xhi, Xlo, (i < L_LAYERS - 1) ? 1 : 0,
            embraw + (size_t)i * G_GRAPHS * H_DIM, slotE, npg);
    }

    final_linear_kernel<<<G_GRAPHS, 32>>>(
        embraw, statsAll, bne_g, bne_b, lin_w, lin_b, out);
}

// round 16
// speedup vs baseline: 1.1069x; 1.0022x over previous
#include <cuda_runtime.h>
#include <cuda_bf16.h>
#include <math.h>
#include <stdint.h>

// ---------------- problem constants ----------------
#define N_NODES   131072
#define G_GRAPHS  1024
#define NPG0      128
#define H_DIM     128
#define E_EDGES   2097152
#define EPG       2048
#define L_LAYERS  3
#define C_CLASSES 10
#define BN_EPS    1e-5f
#define INV_SQRT2 0.70710678118654752440f
#define N_SLOTS   10
#define XPLANE    ((size_t)(N_NODES / 2) * H_DIM)

// ---------------- scratch ----------------
__device__ float g_bufA[(size_t)N_NODES * H_DIM];
__device__ float g_bufB[(size_t)N_NODES * H_DIM];
__device__ float g_X[(size_t)(N_NODES / 2) * H_DIM];   // bf16 hi|lo planes
__device__ float g_embraw[L_LAYERS * G_GRAPHS * H_DIM];
__device__ float g_statsAll[N_SLOTS * 256];
__device__ __nv_bfloat16 g_wimg[7 * 2 * 16384];

// ---------------- helpers ----------------
__device__ __forceinline__ uint32_t smem_u32(const void* p) {
    uint32_t a;
    asm("{ .reg .u64 t; cvta.to.shared.u64 t, %1; cvt.u32.u64 %0, t; }" : "=r"(a) : "l"(p));
    return a;
}
__device__ __forceinline__ uint32_t pack2(__nv_bfloat16 a, __nv_bfloat16 b) {
    __nv_bfloat162 t; t.x = a; t.y = b; return *(uint32_t*)&t;
}
#define LDSM_X4(r, a) \
    asm volatile("ldmatrix.sync.aligned.m8n8.x4.shared.b16 {%0,%1,%2,%3}, [%4];" \
        : "=r"((r)[0]), "=r"((r)[1]), "=r"((r)[2]), "=r"((r)[3]) : "r"(a))
#define LDSM_X4T(r, a) \
    asm volatile("ldmatrix.sync.aligned.m8n8.x4.trans.shared.b16 {%0,%1,%2,%3}, [%4];" \
        : "=r"((r)[0]), "=r"((r)[1]), "=r"((r)[2]), "=r"((r)[3]) : "r"(a))
#define MMA_BF16(d, a, b0, b1) \
    asm volatile("mma.sync.aligned.m16n8k16.row.col.f32.bf16.bf16.f32 " \
        "{%0,%1,%2,%3}, {%4,%5,%6,%7}, {%8,%9}, {%0,%1,%2,%3};" \
        : "+f"((d)[0]), "+f"((d)[1]), "+f"((d)[2]), "+f"((d)[3]) \
        : "r"((a)[0]), "r"((a)[1]), "r"((a)[2]), "r"((a)[3]), "r"(b0), "r"(b1))
#define CP_ASYNC16(saddr, gptr) \
    asm volatile("cp.async.cg.shared.global [%0], [%1], 16;" \
        :: "r"((uint32_t)(saddr)), "l"(gptr) : "memory")
#define CP_COMMIT()  asm volatile("cp.async.commit_group;" ::: "memory")
#define CP_WAIT0()   asm volatile("cp.async.wait_group 0;" ::: "memory")

#define SK_BYTES  272
#define AH_BYTES  144

// ---- shared smem layout ----
#define SB_HI     0
#define SB_LO     34816
#define SA_HI     69632
#define SA_LO     88064
#define SO_BIAS   106496
#define SO_SCALE  107008
#define SO_SHIFT  107520
#define SO_STAT   108032
#define BIG_SMEM  109056

// ---------------- weight bf16 split + stats zero ----------------
__global__ void transw_kernel(const float* __restrict__ w0, const float* __restrict__ w1,
                              const float* __restrict__ w2, __nv_bfloat16* __restrict__ img,
                              float* __restrict__ statsAll) {
    int b = blockIdx.x;
    if (b == 7) {
        for (int i = threadIdx.x; i < N_SLOTS * 256; i += blockDim.x) statsAll[i] = 0.f;
        return;
    }
    const float* W = (b == 0) ? w0 : ((b <= 3) ? w1 + (size_t)(b - 1) * 16384
                                               : w2 + (size_t)(b - 4) * 16384);
    __nv_bfloat16* hi = img + (size_t)b * 32768;
    __nv_bfloat16* lo = hi + 16384;
    for (int i = threadIdx.x; i < 16384; i += blockDim.x) {
        float v = W[i];
        __nv_bfloat16 h = __float2bfloat16(v);
        hi[i] = h;
        lo[i] = __float2bfloat16(v - __bfloat162float(h));
    }
}

// load A half-K from fp32 -> bf16 hi/lo split into SA planes
__device__ __forceinline__ void load_a_half(
    const char* smem, const float4* A4, int kh, int tid, int mode,
    const float* sscale, const float* sshift) {
    #pragma unroll
    for (int it = 0; it < 4; it++) {
        int i = tid + it * 256;
        int row = i >> 3, g = i & 7;
        float4 u = A4[row * 32 + kh * 16 + g * 2];
        float4 v = A4[row * 32 + kh * 16 + g * 2 + 1];
        float xv[8] = {u.x, u.y, u.z, u.w, v.x, v.y, v.z, v.w};
        if (mode) {
            int c0 = kh * 64 + g * 8;
            #pragma unroll
            for (int j = 0; j < 8; j++)
                xv[j] = fmaxf(fmaf(xv[j], sscale[c0 + j], sshift[c0 + j]), 0.f);
        }
        uint32_t hp[4], lp[4];
        #pragma unroll
        for (int j = 0; j < 4; j++) {
            __nv_bfloat16 h0 = __float2bfloat16(xv[2 * j]);
            __nv_bfloat16 h1 = __float2bfloat16(xv[2 * j + 1]);
            hp[j] = pack2(h0, h1);
            lp[j] = pack2(__float2bfloat16(xv[2 * j]     - __bfloat162float(h0)),
                          __float2bfloat16(xv[2 * j + 1] - __bfloat162float(h1)));
        }
        uint32_t off = (uint32_t)row * AH_BYTES + (uint32_t)g * 16;
        *(uint4*)(smem + SA_HI + off) = make_uint4(hp[0], hp[1], hp[2], hp[3]);
        *(uint4*)(smem + SA_LO + off) = make_uint4(lp[0], lp[1], lp[2], lp[3]);
    }
}

// A half-K from pre-split planes via cp.async (pure copy; caller commits/waits)
__device__ __forceinline__ void load_a_half_cpasync(
    uint32_t sbm, const uint4* Hi4, const uint4* Lo4, int kh, int tid) {
    #pragma unroll
    for (int it = 0; it < 4; it++) {
        int i = tid + it * 256;
        int row = i >> 3, g = i & 7;
        int srci = row * 16 + kh * 8 + g;
        uint32_t off = (uint32_t)row * AH_BYTES + (uint32_t)g * 16;
        CP_ASYNC16(sbm + SA_HI + off, Hi4 + srci);
        CP_ASYNC16(sbm + SA_LO + off, Lo4 + srci);
    }
    CP_COMMIT();
}

// 3-term MMA over one K half
__device__ __forceinline__ void mma_half(
    float acc[2][8][4], uint32_t sb, int kh, int wm, int wn, int lane) {
    const uint32_t aA = sb + SA_HI + (uint32_t)(wm * 32 + (lane & 15)) * AH_BYTES
                      + (uint32_t)(lane >> 4) * 16;
    const uint32_t aB = sb + SB_HI + (uint32_t)(lane & 15) * SK_BYTES
                      + (uint32_t)(wn * 128) + (uint32_t)(lane >> 4) * 16;
    #pragma unroll
    for (int ks = 0; ks < 4; ks++) {
        int kidx = kh * 4 + ks;
        uint32_t ah[2][4], al[2][4], bh[4][4], bl[4][4];
        #pragma unroll
        for (int mt = 0; mt < 2; mt++) {
            uint32_t ad = aA + (uint32_t)mt * (16 * AH_BYTES) + (uint32_t)ks * 32;
            LDSM_X4(ah[mt], ad);
            LDSM_X4(al[mt], ad + (SA_LO - SA_HI));
        }
        #pragma unroll
        for (int nt2 = 0; nt2 < 4; nt2++) {
            uint32_t bd = aB + (uint32_t)kidx * (16 * SK_BYTES) + (uint32_t)nt2 * 32;
            LDSM_X4T(bh[nt2], bd);
            LDSM_X4T(bl[nt2], bd + (SB_LO - SB_HI));
        }
        #pragma unroll
        for (int mt = 0; mt < 2; mt++)
            #pragma unroll
            for (int nt = 0; nt < 8; nt++) {
                uint32_t b0h = bh[nt >> 1][(nt & 1) * 2], b1h = bh[nt >> 1][(nt & 1) * 2 + 1];
                uint32_t b0l = bl[nt >> 1][(nt & 1) * 2], b1l = bl[nt >> 1][(nt & 1) * 2 + 1];
                MMA_BF16(acc[mt][nt], ah[mt], b0h, b1h);
                MMA_BF16(acc[mt][nt], ah[mt], b0l, b1l);
                MMA_BF16(acc[mt][nt], al[mt], b0h, b1h);
            }
    }
}

// per-tile epilogue: + bias, smem stat atomics, fp32 store (NO global flush)
__device__ __forceinline__ void epilogue_tile(
    float acc[2][8][4], char* smem, float* Cb, int wm, int wn, int lane) {
    const float* sbias = (float*)(smem + SO_BIAS);
    float* sstat = (float*)(smem + SO_STAT);
    float s[8][2], q[8][2];
    #pragma unroll
    for (int nt = 0; nt < 8; nt++) { s[nt][0] = s[nt][1] = q[nt][0] = q[nt][1] = 0.f; }
    const int cbase = wn * 64 + (lane & 3) * 2;
    const int rbase = wm * 32 + (lane >> 2);
    #pragma unroll
    for (int mt = 0; mt < 2; mt++) {
        int r0 = rbase + mt * 16, r1 = r0 + 8;
        #pragma unroll
        for (int nt = 0; nt < 8; nt++) {
            int c = cbase + nt * 8;
            float b0 = sbias[c], b1 = sbias[c + 1];
            float y0 = acc[mt][nt][0] + b0, y1 = acc[mt][nt][1] + b1;
            float y2 = acc[mt][nt][2] + b0, y3 = acc[mt][nt][3] + b1;
            s[nt][0] += y0 + y2;           s[nt][1] += y1 + y3;
            q[nt][0] += y0 * y0 + y2 * y2; q[nt][1] += y1 * y1 + y3 * y3;
            *(float2*)(Cb + r0 * 128 + c) = make_float2(y0, y1);
            *(float2*)(Cb + r1 * 128 + c) = make_float2(y2, y3);
        }
    }
    #pragma unroll
    for (int off = 16; off >= 4; off >>= 1)
        #pragma unroll
        for (int nt = 0; nt < 8; nt++) {
            s[nt][0] += __shfl_down_sync(0xFFFFFFFFu, s[nt][0], off);
            s[nt][1] += __shfl_down_sync(0xFFFFFFFFu, s[nt][1], off);
            q[nt][0] += __shfl_down_sync(0xFFFFFFFFu, q[nt][0], off);
            q[nt][1] += __shfl_down_sync(0xFFFFFFFFu, q[nt][1], off);
        }
    if (lane < 4) {
        #pragma unroll
        for (int nt = 0; nt < 8; nt++) {
            int c = cbase + nt * 8;
            atomicAdd(&sstat[c],           s[nt][0]);
            atomicAdd(&sstat[c + 1],       s[nt][1]);
            atomicAdd(&sstat[128 + c],     q[nt][0]);
            atomicAdd(&sstat[128 + c + 1], q[nt][1]);
        }
    }
}

// BN coef setup + zero smem stat staging, then sync
__device__ __forceinline__ void setup_coefs(
    char* smem, const float* bias, const float* bnG, const float* bnB,
    const float* statsIn, float nIn, int mode, int tid) {
    float* sbias  = (float*)(smem + SO_BIAS);
    float* sscale = (float*)(smem + SO_SCALE);
    float* sshift = (float*)(smem + SO_SHIFT);
    if (tid < 128) {
        sbias[tid] = bias[tid];
        if (mode) {
            float s = statsIn[tid], q = statsIn[128 + tid];
            float m = s / nIn, v = q / nIn - m * m;
            float sc = bnG[tid] * rsqrtf(v + BN_EPS);
            sscale[tid] = sc;
            sshift[tid] = fmaf(-m, sc, bnB[tid]);
        }
    }
    if (tid < 256) ((float*)(smem + SO_STAT))[tid] = 0.f;
    __syncthreads();
}

// full B planes via cp.async
__device__ __forceinline__ void load_b_planes_async(
    uint32_t sbm, const __nv_bfloat16* Wimg, int tid) {
    const uint4* bh = (const uint4*)Wimg;
    #pragma unroll
    for (int it = 0; it < 8; it++) {
        int i = tid + it * 256;
        int k = i >> 4, g = i & 15;
        uint32_t off = (uint32_t)k * SK_BYTES + (uint32_t)g * 16;
        CP_ASYNC16(sbm + SB_HI + off, bh + i);
        CP_ASYNC16(sbm + SB_LO + off, bh + 2048 + i);
    }
    CP_COMMIT();
}

// ---------------- tc_gemm: 2 tiles per CTA, B resident ----------------
__global__ __launch_bounds__(256, 2) void tc_gemm(
    const float* __restrict__ A, const __nv_bfloat16* __restrict__ Wimg,
    const float* __restrict__ bias,
    const float* __restrict__ bnG, const float* __restrict__ bnB,
    const float* __restrict__ statsIn, float nIn, int mode,
    float* __restrict__ Cf, float* __restrict__ statsOut) {
    extern __shared__ char smem[];
    const uint32_t sb = smem_u32(smem);
    const int tid = threadIdx.x, wid = tid >> 5, lane = tid & 31;
    const int wm = wid >> 1, wn = wid & 1;

    setup_coefs(smem, bias, bnG, bnB, statsIn, nIn, mode, tid);
    load_b_planes_async(sb, Wimg, tid);

    float* sscale = (float*)(smem + SO_SCALE);
    float* sshift = (float*)(smem + SO_SHIFT);

    #pragma unroll
    for (int t = 0; t < 2; t++) {
        const int mb = blockIdx.x * 2 + t;
        const float4* A4 = (const float4*)(A + (size_t)mb * 16384);

        float acc[2][8][4];
        #pragma unroll
        for (int mt = 0; mt < 2; mt++)
            #pragma unroll
            for (int nt = 0; nt < 8; nt++)
                #pragma unroll
                for (int j = 0; j < 4; j++) acc[mt][nt][j] = 0.f;

        load_a_half(smem, A4, 0, tid, mode, sscale, sshift);
        if (t == 0) CP_WAIT0();
        __syncthreads();
        mma_half(acc, sb, 0, wm, wn, lane);
        __syncthreads();
        load_a_half(smem, A4, 1, tid, mode, sscale, sshift);
        __syncthreads();
        mma_half(acc, sb, 1, wm, wn, lane);
        __syncthreads();   // protects SA for next tile's load / pre-epilogue order

        epilogue_tile(acc, smem, Cf + (size_t)mb * 16384, wm, wn, lane);
    }
    __syncthreads();
    if (tid < 256) atomicAdd(&statsOut[tid], ((float*)(smem + SO_STAT))[tid]);
}

// ---------------- fused layer: H = (I+A)(op(x)@W1) + b1, + stats ----------------
// afmt 0: A fp32 (opt. BN). afmt 2: A pre-split bf16 planes (cp.async copy).
__global__ __launch_bounds__(256, 2) void fused_layer(
    const float* __restrict__ A,
    const __nv_bfloat16* __restrict__ Ahi, const __nv_bfloat16* __restrict__ Alo,
    const __nv_bfloat16* __restrict__ W1img,
    const int* __restrict__ src, const int* __restrict__ dst,
    const float* __restrict__ bias,
    const float* __restrict__ bnG, const float* __restrict__ bnB,
    const float* __restrict__ statsIn, float nIn, int afmt, int mode,
    float* __restrict__ H, float* __restrict__ statsOut, int layer) {
    extern __shared__ char smem[];
    const uint32_t sb = smem_u32(smem);
    const int tid = threadIdx.x, wid = tid >> 5, lane = tid & 31;
    const int wm = wid >> 1, wn = wid & 1;

    setup_coefs(smem, bias, bnG, bnB, statsIn, nIn, mode, tid);
    load_b_planes_async(sb, W1img, tid);

    const float4* A4 = (const float4*)(A + (size_t)blockIdx.x * 16384);
    const uint4* Hi4 = (const uint4*)(Ahi + (size_t)blockIdx.x * 16384);
    const uint4* Lo4 = (const uint4*)(Alo + (size_t)blockIdx.x * 16384);
    float* sscale = (float*)(smem + SO_SCALE);
    float* sshift = (float*)(smem + SO_SHIFT);

    float acc[2][8][4];
    #pragma unroll
    for (int mt = 0; mt < 2; mt++)
        #pragma unroll
        for (int nt = 0; nt < 8; nt++)
            #pragma unroll
            for (int j = 0; j < 4; j++) acc[mt][nt][j] = 0.f;

    if (afmt == 0) load_a_half(smem, A4, 0, tid, mode, sscale, sshift);
    else           load_a_half_cpasync(sb, Hi4, Lo4, 0, tid);
    CP_WAIT0();
    __syncthreads();
    mma_half(acc, sb, 0, wm, wn, lane);
    __syncthreads();
    if (afmt == 0) {
        load_a_half(smem, A4, 1, tid, mode, sscale, sshift);
    } else {
        load_a_half_cpasync(sb, Hi4, Lo4, 1, tid);
        CP_WAIT0();
    }
    __syncthreads();
    mma_half(acc, sb, 1, wm, wn, lane);
    __syncthreads();

    // Y fragments -> bf16 hi/lo planes in smem (overwrite W1 planes); zero cnt region
    {
        const int cbase = wn * 64 + (lane & 3) * 2;
        const int rbase = wm * 32 + (lane >> 2);
        #pragma unroll
        for (int mt = 0; mt < 2; mt++) {
            int r0 = rbase + mt * 16, r1 = r0 + 8;
            #pragma unroll
            for (int nt = 0; nt < 8; nt++) {
                int c = cbase + nt * 8;
                float y0 = acc[mt][nt][0], y1 = acc[mt][nt][1];
                float y2 = acc[mt][nt][2], y3 = acc[mt][nt][3];
                __nv_bfloat16 h0 = __float2bfloat16(y0), h1 = __float2bfloat16(y1);
                __nv_bfloat16 h2 = __float2bfloat16(y2), h3 = __float2bfloat16(y3);
                *(uint32_t*)(smem + SB_HI + (uint32_t)r0 * SK_BYTES + (uint32_t)c * 2) = pack2(h0, h1);
                *(uint32_t*)(smem + SB_HI + (uint32_t)r1 * SK_BYTES + (uint32_t)c * 2) = pack2(h2, h3);
                *(uint32_t*)(smem + SB_LO + (uint32_t)r0 * SK_BYTES + (uint32_t)c * 2) =
                    pack2(__float2bfloat16(y0 - __bfloat162float(h0)),
                          __float2bfloat16(y1 - __bfloat162float(h1)));
                *(uint32_t*)(smem + SB_LO + (uint32_t)r1 * SK_BYTES + (uint32_t)c * 2) =
                    pack2(__float2bfloat16(y2 - __bfloat162float(h2)),
                          __float2bfloat16(y3 - __bfloat162float(h3)));
            }
        }
        uint4* az = (uint4*)(smem + SA_HI);
        for (int i = tid; i < 2176; i += 256) az[i] = make_uint4(0, 0, 0, 0);
    }
    __syncthreads();

    // packed 16-bit pair counts via int atomics (rows of 68 words = 272 B)
    {
        int* cntw = (int*)(smem + SA_HI);
        const int gb = 1 << layer, npg = NPG0 >> layer;
        const int g0 = blockIdx.x * gb;
        const int tot = gb * EPG;
        for (int idx = tid; idx < tot; idx += 256) {
            int j = idx >> 11;
            int e = (g0 + j) * EPG + (idx & 2047);
            int nb = (g0 + j) * NPG0;
            int d = (dst[e] - nb) >> layer;
            int s = (src[e] - nb) >> layer;
            int row = j * npg + d, col = j * npg + s;
            atomicAdd(&cntw[row * 68 + (col >> 1)], 1 << ((col & 1) * 16));
        }
    }
    __syncthreads();

    // counts -> bf16 Abar (+I), in place
    {
        uint32_t* cw = (uint32_t*)(smem + SA_HI);
        for (int i = tid; i < 128 * 64; i += 256) {
            int row = i >> 6, w = i & 63;
            int col = w * 2;
            uint32_t v = cw[row * 68 + w];
            float v0 = (float)(v & 0xFFFFu) + ((row == col)     ? 1.f : 0.f);
            float v1 = (float)(v >> 16)     + ((row == col + 1) ? 1.f : 0.f);
            cw[row * 68 + w] = pack2(__float2bfloat16(v0), __float2bfloat16(v1));
        }
    }
    __syncthreads();

    // agg MMA: acc2 = Abar @ (Yhi + Ylo)
    float acc2[2][8][4];
    #pragma unroll
    for (int mt = 0; mt < 2; mt++)
        #pragma unroll
        for (int nt = 0; nt < 8; nt++)
            #pragma unroll
            for (int j = 0; j < 4; j++) acc2[mt][nt][j] = 0.f;
    {
        const uint32_t aA = sb + SA_HI + (uint32_t)(wm * 32 + (lane & 15)) * SK_BYTES
                          + (uint32_t)(lane >> 4) * 16;
        const uint32_t aB = sb + SB_HI + (uint32_t)(lane & 15) * SK_BYTES
                          + (uint32_t)(wn * 128) + (uint32_t)(lane >> 4) * 16;
        #pragma unroll
        for (int ks = 0; ks < 8; ks++) {
            uint32_t a[2][4], bh[4][4], bl[4][4];
            #pragma unroll
            for (int mt = 0; mt < 2; mt++)
                LDSM_X4(a[mt], aA + (uint32_t)mt * (16 * SK_BYTES) + (uint32_t)ks * 32);
            #pragma unroll
            for (int nt2 = 0; nt2 < 4; nt2++) {
                uint32_t bd = aB + (uint32_t)ks * (16 * SK_BYTES) + (uint32_t)nt2 * 32;
                LDSM_X4T(bh[nt2], bd);
                LDSM_X4T(bl[nt2], bd + (SB_LO - SB_HI));
            }
            #pragma unroll
            for (int mt = 0; mt < 2; mt++)
                #pragma unroll
                for (int nt = 0; nt < 8; nt++) {
                    uint32_t b0h = bh[nt >> 1][(nt & 1) * 2], b1h = bh[nt >> 1][(nt & 1) * 2 + 1];
                    uint32_t b0l = bl[nt >> 1][(nt & 1) * 2], b1l = bl[nt >> 1][(nt & 1) * 2 + 1];
                    MMA_BF16(acc2[mt][nt], a[mt], b0h, b1h);
                    MMA_BF16(acc2[mt][nt], a[mt], b0l, b1l);
                }
        }
    }
    __syncthreads();
    epilogue_tile(acc2, smem, H + (size_t)blockIdx.x * 16384, wm, wn, lane);
    __syncthreads();
    if (tid < 256) atomicAdd(&statsOut[tid], ((float*)(smem + SO_STAT))[tid]);
}

// ---------------- pool: inline BN+relu -> Haar -> plane out + embd sums/stats --
__global__ __launch_bounds__(256) void pool_kernel(
    const float* __restrict__ Hin,
    const float* __restrict__ bnG, const float* __restrict__ bnB,
    const float* __restrict__ statsIn, float nIn,
    __nv_bfloat16* __restrict__ Xhi, __nv_bfloat16* __restrict__ Xlo, int writeX,
    float* __restrict__ embraw, float* __restrict__ statsOut, int npg_in) {
    __shared__ float es[128], psc[128], psh[128];
    const int g = blockIdx.x, tid = threadIdx.x;
    if (tid < 128) {
        es[tid] = 0.f;
        float sv = statsIn[tid], qv = statsIn[128 + tid];
        float m = sv / nIn, v = qv / nIn - m * m;
        float c_ = bnG[tid] * rsqrtf(v + BN_EPS);
        psc[tid] = c_;
        psh[tid] = fmaf(-m, c_, bnB[tid]);
    }
    __syncthreads();

    const int npg_out = npg_in >> 1;
    const float4* in4 = (const float4*)(Hin + (size_t)g * npg_in * 128);
    const size_t xbase = (size_t)g * npg_out * 128;

    const int cfix = (tid & 31) * 4;
    float a0 = 0.f, a1 = 0.f, a2 = 0.f, a3 = 0.f;

    for (int i = tid; i < npg_out * 32; i += 256) {
        int row = i >> 5, c = cfix;
        float4 a = in4[(2 * row) * 32 + (i & 31)];
        float4 b = in4[(2 * row + 1) * 32 + (i & 31)];
        float4 p;
        p.x = (fmaxf(fmaf(a.x, psc[c+0], psh[c+0]), 0.f) + fmaxf(fmaf(b.x, psc[c+0], psh[c+0]), 0.f)) * INV_SQRT2;
        p.y = (fmaxf(fmaf(a.y, psc[c+1], psh[c+1]), 0.f) + fmaxf(fmaf(b.y, psc[c+1], psh[c+1]), 0.f)) * INV_SQRT2;
        p.z = (fmaxf(fmaf(a.z, psc[c+2], psh[c+2]), 0.f) + fmaxf(fmaf(b.z, psc[c+2], psh[c+2]), 0.f)) * INV_SQRT2;
        p.w = (fmaxf(fmaf(a.w, psc[c+3], psh[c+3]), 0.f) + fmaxf(fmaf(b.w, psc[c+3], psh[c+3]), 0.f)) * INV_SQRT2;
        if (writeX) {
            __nv_bfloat16 hx = __float2bfloat16(p.x), hy = __float2bfloat16(p.y);
            __nv_bfloat16 hz = __float2bfloat16(p.z), hw = __float2bfloat16(p.w);
            size_t e = xbase + (size_t)row * 128 + c;
            *(uint32_t*)(Xhi + e)     = pack2(hx, hy);
            *(uint32_t*)(Xhi + e + 2) = pack2(hz, hw);
            *(uint32_t*)(Xlo + e)     = pack2(__float2bfloat16(p.x - __bfloat162float(hx)),
                                              __float2bfloat16(p.y - __bfloat162float(hy)));
            *(uint32_t*)(Xlo + e + 2) = pack2(__float2bfloat16(p.z - __bfloat162float(hz)),
                                              __float2bfloat16(p.w - __bfloat162float(hw)));
        }
        a0 += p.x; a1 += p.y; a2 += p.z; a3 += p.w;
    }
    atomicAdd(&es[cfix + 0], a0);
    atomicAdd(&es[cfix + 1], a1);
    atomicAdd(&es[cfix + 2], a2);
    atomicAdd(&es[cfix + 3], a3);
    __syncthreads();
    if (tid < 128) {
        float v = es[tid];
        embraw[g * 128 + tid] = v;
        atomicAdd(&statsOut[tid], v);
        atomicAdd(&statsOut[128 + tid], v * v);
    }
}

// ---------------- final linear with inline embedding-BN ------------------------
__global__ void final_linear_kernel(
    const float* __restrict__ embraw, const float* __restrict__ statsAll,
    const float* __restrict__ bneG, const float* __restrict__ bneB,
    const float* __restrict__ W, const float* __restrict__ b, float* __restrict__ out) {
    const int g = blockIdx.x, lane = threadIdx.x;
    float acc[C_CLASSES];
    #pragma unroll
    for (int c = 0; c < C_CLASSES; c++) acc[c] = 0.f;
    for (int k = lane; k < L_LAYERS * H_DIM; k += 32) {
        int layer = k >> 7, c = k & 127;
        const float* st = statsAll + (3 + 3 * layer) * 256;
        float m = st[c] / (float)G_GRAPHS;
        float v = st[128 + c] / (float)G_GRAPHS - m * m;
        float sc = bneG[layer * 128 + c] * rsqrtf(v + BN_EPS);
        float sh = fmaf(-m, sc, bneB[layer * 128 + c]);
        float e = fmaxf(fmaf(embraw[(size_t)layer * G_GRAPHS * 128 + g * 128 + c], sc, sh), 0.f);
        #pragma unroll
        for (int c10 = 0; c10 < C_CLASSES; c10++)
            acc[c10] = fmaf(e, W[k * C_CLASSES + c10], acc[c10]);
    }
    #pragma unroll
    for (int off = 16; off > 0; off >>= 1)
        #pragma unroll
        for (int c = 0; c < C_CLASSES; c++)
            acc[c] += __shfl_down_sync(0xFFFFFFFFu, acc[c], off);
    if (lane == 0) {
        #pragma unroll
        for (int c = 0; c < C_CLASSES; c++)
            out[g * C_CLASSES + c] = acc[c] + b[c];
    }
}

// ---------------- host orchestration ----------------
extern "C" void kernel_launch(void* const* d_in, const int* in_sizes, int n_in,
                              void* d_out, int out_size) {
    const float* x           = (const float*)d_in[0];
    const int*   ei          = (const int*)d_in[1];
    const int*   src         = ei;
    const int*   dst         = ei + E_EDGES;
    const float* lin_start_w = (const float*)d_in[2];
    const float* lin_start_b = (const float*)d_in[3];
    const float* bn_start_g  = (const float*)d_in[4];
    const float* bn_start_b  = (const float*)d_in[5];
    const float* conv_w1     = (const float*)d_in[6];
    const float* conv_b1     = (const float*)d_in[7];
    const float* conv_bn_g   = (const float*)d_in[8];
    const float* conv_bn_b   = (const float*)d_in[9];
    const float* conv_w2     = (const float*)d_in[10];
    const float* conv_b2     = (const float*)d_in[11];
    const float* bn_g        = (const float*)d_in[12];
    const float* bn_b        = (const float*)d_in[13];
    const float* bne_g       = (const float*)d_in[14];
    const float* bne_b       = (const float*)d_in[15];
    const float* lin_w       = (const float*)d_in[16];
    const float* lin_b       = (const float*)d_in[17];
    float* out = (float*)d_out;

    float *bufA, *bufB, *bufX, *embraw, *statsAll;
    __nv_bfloat16* wimg;
    cudaGetSymbolAddress((void**)&bufA,     g_bufA);
    cudaGetSymbolAddress((void**)&bufB,     g_bufB);
    cudaGetSymbolAddress((void**)&bufX,     g_X);
    cudaGetSymbolAddress((void**)&embraw,   g_embraw);
    cudaGetSymbolAddress((void**)&statsAll, g_statsAll);
    cudaGetSymbolAddress((void**)&wimg,     g_wimg);

    __nv_bfloat16* Xhi = (__nv_bfloat16*)bufX;
    __nv_bfloat16* Xlo = Xhi + XPLANE;

    cudaFuncSetAttribute(tc_gemm, cudaFuncAttributeMaxDynamicSharedMemorySize, BIG_SMEM);
    cudaFuncSetAttribute(fused_layer, cudaFuncAttributeMaxDynamicSharedMemorySize, BIG_SMEM);

    transw_kernel<<<8, 256>>>(lin_start_w, conv_w1, conv_w2, wimg, statsAll);

    float* slot0 = statsAll;

    // Stage 0: bufA = x @ W_start + b  (2 tiles/CTA)
    tc_gemm<<<N_NODES / 256, 256, BIG_SMEM>>>(
        x, wimg, lin_start_b, nullptr, nullptr, nullptr, 0.f, 0, bufA, slot0);

    for (int i = 0; i < L_LAYERS; i++) {
        const int n = N_NODES >> i;
        const int npg = NPG0 >> i;
        float* slotH = statsAll + (1 + 3 * i) * 256;
        float* slotG = statsAll + (2 + 3 * i) * 256;
        float* slotE = statsAll + (3 + 3 * i) * 256;

        // fused: H = (I+A)(op(x)@W1) + b1
        fused_layer<<<n / 128, 256, BIG_SMEM>>>(
            (i == 0) ? (const float*)bufA : nullptr,
            (i == 0) ? nullptr : Xhi, (i == 0) ? nullptr : Xlo,
            wimg + (size_t)(1 + i) * 32768, src, dst, conv_b1 + i * H_DIM,
            (i == 0) ? bn_start_g : nullptr, (i == 0) ? bn_start_b : nullptr,
            (i == 0) ? slot0 : nullptr, (float)N_NODES,
            (i == 0) ? 0 : 2, (i == 0) ? 1 : 0,
            bufA, slotH, i);

        // G = relu(bn(H)) @ W2 + b2  (2 tiles/CTA)
        tc_gemm<<<n / 256, 256, BIG_SMEM>>>(
            bufA, wimg + (size_t)(4 + i) * 32768, conv_b2 + i * H_DIM,
            conv_bn_g + i * H_DIM, conv_bn_b + i * H_DIM, slotH, (float)n, 1,
            bufB, slotG);

        // pool: bn(G)+relu -> Haar -> X planes (skip write on last layer)
        pool_kernel<<<G_GRAPHS, 256>>>(
            bufB, bn_g + i * H_DIM, bn_b + i * H_DIM, slotG, (float)n,
            Xhi, Xlo, (i < L_LAYERS - 1) ? 1 : 0,
            embraw + (size_t)i * G_GRAPHS * H_DIM, slotE, npg);
    }

    final_linear_kernel<<<G_GRAPHS, 32>>>(
        embraw, statsAll, bne_g, bne_b, lin_w, lin_b, out);
}

// round 17
// speedup vs baseline: 1.1583x; 1.0464x over previous
#include <cuda_runtime.h>
#include <cuda_bf16.h>
#include <math.h>
#include <stdint.h>

// ---------------- problem constants ----------------
#define N_NODES   131072
#define G_GRAPHS  1024
#define NPG0      128
#define H_DIM     128
#define E_EDGES   2097152
#define EPG       2048
#define L_LAYERS  3
#define C_CLASSES 10
#define BN_EPS    1e-5f
#define INV_SQRT2 0.70710678118654752440f
#define N_SLOTS   10
#define XPLANE    ((size_t)(N_NODES / 2) * H_DIM)
#define MAXCTAS   296            // 148 SMs x 2 resident CTAs

// ---------------- scratch ----------------
__device__ float g_bufA[(size_t)N_NODES * H_DIM];
__device__ float g_bufB[(size_t)N_NODES * H_DIM];
__device__ float g_X[(size_t)(N_NODES / 2) * H_DIM];   // bf16 hi|lo planes
__device__ float g_embraw[L_LAYERS * G_GRAPHS * H_DIM];
__device__ float g_statsAll[N_SLOTS * 256];
__device__ __nv_bfloat16 g_wimg[7 * 2 * 16384];

// ---------------- helpers ----------------
__device__ __forceinline__ uint32_t smem_u32(const void* p) {
    uint32_t a;
    asm("{ .reg .u64 t; cvta.to.shared.u64 t, %1; cvt.u32.u64 %0, t; }" : "=r"(a) : "l"(p));
    return a;
}
__device__ __forceinline__ uint32_t pack2(__nv_bfloat16 a, __nv_bfloat16 b) {
    __nv_bfloat162 t; t.x = a; t.y = b; return *(uint32_t*)&t;
}
#define LDSM_X4(r, a) \
    asm volatile("ldmatrix.sync.aligned.m8n8.x4.shared.b16 {%0,%1,%2,%3}, [%4];" \
        : "=r"((r)[0]), "=r"((r)[1]), "=r"((r)[2]), "=r"((r)[3]) : "r"(a))
#define LDSM_X4T(r, a) \
    asm volatile("ldmatrix.sync.aligned.m8n8.x4.trans.shared.b16 {%0,%1,%2,%3}, [%4];" \
        : "=r"((r)[0]), "=r"((r)[1]), "=r"((r)[2]), "=r"((r)[3]) : "r"(a))
#define MMA_BF16(d, a, b0, b1) \
    asm volatile("mma.sync.aligned.m16n8k16.row.col.f32.bf16.bf16.f32 " \
        "{%0,%1,%2,%3}, {%4,%5,%6,%7}, {%8,%9}, {%0,%1,%2,%3};" \
        : "+f"((d)[0]), "+f"((d)[1]), "+f"((d)[2]), "+f"((d)[3]) \
        : "r"((a)[0]), "r"((a)[1]), "r"((a)[2]), "r"((a)[3]), "r"(b0), "r"(b1))
#define CP_ASYNC16(saddr, gptr) \
    asm volatile("cp.async.cg.shared.global [%0], [%1], 16;" \
        :: "r"((uint32_t)(saddr)), "l"(gptr) : "memory")
#define CP_COMMIT()  asm volatile("cp.async.commit_group;" ::: "memory")
#define CP_WAIT0()   asm volatile("cp.async.wait_group 0;" ::: "memory")

#define SK_BYTES  272
#define AH_BYTES  144

// ---- shared smem layout ----
#define SB_HI     0
#define SB_LO     34816
#define SA_HI     69632
#define SA_LO     88064
#define SO_BIAS   106496
#define SO_SCALE  107008
#define SO_SHIFT  107520
#define SO_STAT   108032
#define BIG_SMEM  109056

// ---------------- weight bf16 split + stats zero ----------------
__global__ void transw_kernel(const float* __restrict__ w0, const float* __restrict__ w1,
                              const float* __restrict__ w2, __nv_bfloat16* __restrict__ img,
                              float* __restrict__ statsAll) {
    int b = blockIdx.x;
    if (b == 7) {
        for (int i = threadIdx.x; i < N_SLOTS * 256; i += blockDim.x) statsAll[i] = 0.f;
        return;
    }
    const float* W = (b == 0) ? w0 : ((b <= 3) ? w1 + (size_t)(b - 1) * 16384
                                               : w2 + (size_t)(b - 4) * 16384);
    __nv_bfloat16* hi = img + (size_t)b * 32768;
    __nv_bfloat16* lo = hi + 16384;
    for (int i = threadIdx.x; i < 16384; i += blockDim.x) {
        float v = W[i];
        __nv_bfloat16 h = __float2bfloat16(v);
        hi[i] = h;
        lo[i] = __float2bfloat16(v - __bfloat162float(h));
    }
}

// load A half-K from fp32 -> bf16 hi/lo split into SA planes
__device__ __forceinline__ void load_a_half(
    const char* smem, const float4* A4, int kh, int tid, int mode,
    const float* sscale, const float* sshift) {
    #pragma unroll
    for (int it = 0; it < 4; it++) {
        int i = tid + it * 256;
        int row = i >> 3, g = i & 7;
        float4 u = A4[row * 32 + kh * 16 + g * 2];
        float4 v = A4[row * 32 + kh * 16 + g * 2 + 1];
        float xv[8] = {u.x, u.y, u.z, u.w, v.x, v.y, v.z, v.w};
        if (mode) {
            int c0 = kh * 64 + g * 8;
            #pragma unroll
            for (int j = 0; j < 8; j++)
                xv[j] = fmaxf(fmaf(xv[j], sscale[c0 + j], sshift[c0 + j]), 0.f);
        }
        uint32_t hp[4], lp[4];
        #pragma unroll
        for (int j = 0; j < 4; j++) {
            __nv_bfloat16 h0 = __float2bfloat16(xv[2 * j]);
            __nv_bfloat16 h1 = __float2bfloat16(xv[2 * j + 1]);
            hp[j] = pack2(h0, h1);
            lp[j] = pack2(__float2bfloat16(xv[2 * j]     - __bfloat162float(h0)),
                          __float2bfloat16(xv[2 * j + 1] - __bfloat162float(h1)));
        }
        uint32_t off = (uint32_t)row * AH_BYTES + (uint32_t)g * 16;
        *(uint4*)(smem + SA_HI + off) = make_uint4(hp[0], hp[1], hp[2], hp[3]);
        *(uint4*)(smem + SA_LO + off) = make_uint4(lp[0], lp[1], lp[2], lp[3]);
    }
}

// A half-K from pre-split planes via cp.async (pure copy; caller commits/waits)
__device__ __forceinline__ void load_a_half_cpasync(
    uint32_t sbm, const uint4* Hi4, const uint4* Lo4, int kh, int tid) {
    #pragma unroll
    for (int it = 0; it < 4; it++) {
        int i = tid + it * 256;
        int row = i >> 3, g = i & 7;
        int srci = row * 16 + kh * 8 + g;
        uint32_t off = (uint32_t)row * AH_BYTES + (uint32_t)g * 16;
        CP_ASYNC16(sbm + SA_HI + off, Hi4 + srci);
        CP_ASYNC16(sbm + SA_LO + off, Lo4 + srci);
    }
    CP_COMMIT();
}

// 3-term MMA over one K half
__device__ __forceinline__ void mma_half(
    float acc[2][8][4], uint32_t sb, int kh, int wm, int wn, int lane) {
    const uint32_t aA = sb + SA_HI + (uint32_t)(wm * 32 + (lane & 15)) * AH_BYTES
                      + (uint32_t)(lane >> 4) * 16;
    const uint32_t aB = sb + SB_HI + (uint32_t)(lane & 15) * SK_BYTES
                      + (uint32_t)(wn * 128) + (uint32_t)(lane >> 4) * 16;
    #pragma unroll
    for (int ks = 0; ks < 4; ks++) {
        int kidx = kh * 4 + ks;
        uint32_t ah[2][4], al[2][4], bh[4][4], bl[4][4];
        #pragma unroll
        for (int mt = 0; mt < 2; mt++) {
            uint32_t ad = aA + (uint32_t)mt * (16 * AH_BYTES) + (uint32_t)ks * 32;
            LDSM_X4(ah[mt], ad);
            LDSM_X4(al[mt], ad + (SA_LO - SA_HI));
        }
        #pragma unroll
        for (int nt2 = 0; nt2 < 4; nt2++) {
            uint32_t bd = aB + (uint32_t)kidx * (16 * SK_BYTES) + (uint32_t)nt2 * 32;
            LDSM_X4T(bh[nt2], bd);
            LDSM_X4T(bl[nt2], bd + (SB_LO - SB_HI));
        }
        #pragma unroll
        for (int mt = 0; mt < 2; mt++)
            #pragma unroll
            for (int nt = 0; nt < 8; nt++) {
                uint32_t b0h = bh[nt >> 1][(nt & 1) * 2], b1h = bh[nt >> 1][(nt & 1) * 2 + 1];
                uint32_t b0l = bl[nt >> 1][(nt & 1) * 2], b1l = bl[nt >> 1][(nt & 1) * 2 + 1];
                MMA_BF16(acc[mt][nt], ah[mt], b0h, b1h);
                MMA_BF16(acc[mt][nt], ah[mt], b0l, b1l);
                MMA_BF16(acc[mt][nt], al[mt], b0h, b1h);
            }
    }
}

// per-tile epilogue: + bias, smem stat atomics, fp32 store (NO global flush)
__device__ __forceinline__ void epilogue_tile(
    float acc[2][8][4], char* smem, float* Cb, int wm, int wn, int lane) {
    const float* sbias = (float*)(smem + SO_BIAS);
    float* sstat = (float*)(smem + SO_STAT);
    float s[8][2], q[8][2];
    #pragma unroll
    for (int nt = 0; nt < 8; nt++) { s[nt][0] = s[nt][1] = q[nt][0] = q[nt][1] = 0.f; }
    const int cbase = wn * 64 + (lane & 3) * 2;
    const int rbase = wm * 32 + (lane >> 2);
    #pragma unroll
    for (int mt = 0; mt < 2; mt++) {
        int r0 = rbase + mt * 16, r1 = r0 + 8;
        #pragma unroll
        for (int nt = 0; nt < 8; nt++) {
            int c = cbase + nt * 8;
            float b0 = sbias[c], b1 = sbias[c + 1];
            float y0 = acc[mt][nt][0] + b0, y1 = acc[mt][nt][1] + b1;
            float y2 = acc[mt][nt][2] + b0, y3 = acc[mt][nt][3] + b1;
            s[nt][0] += y0 + y2;           s[nt][1] += y1 + y3;
            q[nt][0] += y0 * y0 + y2 * y2; q[nt][1] += y1 * y1 + y3 * y3;
            *(float2*)(Cb + r0 * 128 + c) = make_float2(y0, y1);
            *(float2*)(Cb + r1 * 128 + c) = make_float2(y2, y3);
        }
    }
    #pragma unroll
    for (int off = 16; off >= 4; off >>= 1)
        #pragma unroll
        for (int nt = 0; nt < 8; nt++) {
            s[nt][0] += __shfl_down_sync(0xFFFFFFFFu, s[nt][0], off);
            s[nt][1] += __shfl_down_sync(0xFFFFFFFFu, s[nt][1], off);
            q[nt][0] += __shfl_down_sync(0xFFFFFFFFu, q[nt][0], off);
            q[nt][1] += __shfl_down_sync(0xFFFFFFFFu, q[nt][1], off);
        }
    if (lane < 4) {
        #pragma unroll
        for (int nt = 0; nt < 8; nt++) {
            int c = cbase + nt * 8;
            atomicAdd(&sstat[c],           s[nt][0]);
            atomicAdd(&sstat[c + 1],       s[nt][1]);
            atomicAdd(&sstat[128 + c],     q[nt][0]);
            atomicAdd(&sstat[128 + c + 1], q[nt][1]);
        }
    }
}

// BN coef setup + zero smem stat staging, then sync
__device__ __forceinline__ void setup_coefs(
    char* smem, const float* bias, const float* bnG, const float* bnB,
    const float* statsIn, float nIn, int mode, int tid) {
    float* sbias  = (float*)(smem + SO_BIAS);
    float* sscale = (float*)(smem + SO_SCALE);
    float* sshift = (float*)(smem + SO_SHIFT);
    if (tid < 128) {
        sbias[tid] = bias[tid];
        if (mode) {
            float s = statsIn[tid], q = statsIn[128 + tid];
            float m = s / nIn, v = q / nIn - m * m;
            float sc = bnG[tid] * rsqrtf(v + BN_EPS);
            sscale[tid] = sc;
            sshift[tid] = fmaf(-m, sc, bnB[tid]);
        }
    }
    if (tid < 256) ((float*)(smem + SO_STAT))[tid] = 0.f;
    __syncthreads();
}

// full B planes via cp.async
__device__ __forceinline__ void load_b_planes_async(
    uint32_t sbm, const __nv_bfloat16* Wimg, int tid) {
    const uint4* bh = (const uint4*)Wimg;
    #pragma unroll
    for (int it = 0; it < 8; it++) {
        int i = tid + it * 256;
        int k = i >> 4, g = i & 15;
        uint32_t off = (uint32_t)k * SK_BYTES + (uint32_t)g * 16;
        CP_ASYNC16(sbm + SB_HI + off, bh + i);
        CP_ASYNC16(sbm + SB_LO + off, bh + 2048 + i);
    }
    CP_COMMIT();
}

// ---------------- tc_gemm: persistent grid-stride, B resident ----------------
__global__ __launch_bounds__(256, 2) void tc_gemm(
    const float* __restrict__ A, const __nv_bfloat16* __restrict__ Wimg,
    const float* __restrict__ bias,
    const float* __restrict__ bnG, const float* __restrict__ bnB,
    const float* __restrict__ statsIn, float nIn, int mode,
    float* __restrict__ Cf, float* __restrict__ statsOut, int ntiles) {
    extern __shared__ char smem[];
    const uint32_t sb = smem_u32(smem);
    const int tid = threadIdx.x, wid = tid >> 5, lane = tid & 31;
    const int wm = wid >> 1, wn = wid & 1;

    setup_coefs(smem, bias, bnG, bnB, statsIn, nIn, mode, tid);
    load_b_planes_async(sb, Wimg, tid);

    float* sscale = (float*)(smem + SO_SCALE);
    float* sshift = (float*)(smem + SO_SHIFT);

    int first = 1;
    for (int mb = blockIdx.x; mb < ntiles; mb += gridDim.x) {
        const float4* A4 = (const float4*)(A + (size_t)mb * 16384);

        float acc[2][8][4];
        #pragma unroll
        for (int mt = 0; mt < 2; mt++)
            #pragma unroll
            for (int nt = 0; nt < 8; nt++)
                #pragma unroll
                for (int j = 0; j < 4; j++) acc[mt][nt][j] = 0.f;

        load_a_half(smem, A4, 0, tid, mode, sscale, sshift);
        if (first) { CP_WAIT0(); first = 0; }
        __syncthreads();
        mma_half(acc, sb, 0, wm, wn, lane);
        __syncthreads();
        load_a_half(smem, A4, 1, tid, mode, sscale, sshift);
        __syncthreads();
        mma_half(acc, sb, 1, wm, wn, lane);
        __syncthreads();   // SA reuse safety for next iteration

        epilogue_tile(acc, smem, Cf + (size_t)mb * 16384, wm, wn, lane);
    }
    __syncthreads();
    if (tid < 256) atomicAdd(&statsOut[tid], ((float*)(smem + SO_STAT))[tid]);
}

// ---------------- fused layer: H = (I+A)(op(x)@W1) + b1, + stats ----------------
__global__ __launch_bounds__(256, 2) void fused_layer(
    const float* __restrict__ A,
    const __nv_bfloat16* __restrict__ Ahi, const __nv_bfloat16* __restrict__ Alo,
    const __nv_bfloat16* __restrict__ W1img,
    const int* __restrict__ src, const int* __restrict__ dst,
    const float* __restrict__ bias,
    const float* __restrict__ bnG, const float* __restrict__ bnB,
    const float* __restrict__ statsIn, float nIn, int afmt, int mode,
    float* __restrict__ H, float* __restrict__ statsOut, int layer) {
    extern __shared__ char smem[];
    const uint32_t sb = smem_u32(smem);
    const int tid = threadIdx.x, wid = tid >> 5, lane = tid & 31;
    const int wm = wid >> 1, wn = wid & 1;

    setup_coefs(smem, bias, bnG, bnB, statsIn, nIn, mode, tid);
    load_b_planes_async(sb, W1img, tid);

    const float4* A4 = (const float4*)(A + (size_t)blockIdx.x * 16384);
    const uint4* Hi4 = (const uint4*)(Ahi + (size_t)blockIdx.x * 16384);
    const uint4* Lo4 = (const uint4*)(Alo + (size_t)blockIdx.x * 16384);
    float* sscale = (float*)(smem + SO_SCALE);
    float* sshift = (float*)(smem + SO_SHIFT);

    float acc[2][8][4];
    #pragma unroll
    for (int mt = 0; mt < 2; mt++)
        #pragma unroll
        for (int nt = 0; nt < 8; nt++)
            #pragma unroll
            for (int j = 0; j < 4; j++) acc[mt][nt][j] = 0.f;

    if (afmt == 0) load_a_half(smem, A4, 0, tid, mode, sscale, sshift);
    else           load_a_half_cpasync(sb, Hi4, Lo4, 0, tid);
    CP_WAIT0();
    __syncthreads();
    mma_half(acc, sb, 0, wm, wn, lane);
    __syncthreads();
    if (afmt == 0) {
        load_a_half(smem, A4, 1, tid, mode, sscale, sshift);
    } else {
        load_a_half_cpasync(sb, Hi4, Lo4, 1, tid);
        CP_WAIT0();
    }
    __syncthreads();
    mma_half(acc, sb, 1, wm, wn, lane);
    __syncthreads();

    // Y fragments -> bf16 hi/lo planes in smem (overwrite W1 planes); zero cnt region
    {
        const int cbase = wn * 64 + (lane & 3) * 2;
        const int rbase = wm * 32 + (lane >> 2);
        #pragma unroll
        for (int mt = 0; mt < 2; mt++) {
            int r0 = rbase + mt * 16, r1 = r0 + 8;
            #pragma unroll
            for (int nt = 0; nt < 8; nt++) {
                int c = cbase + nt * 8;
                float y0 = acc[mt][nt][0], y1 = acc[mt][nt][1];
                float y2 = acc[mt][nt][2], y3 = acc[mt][nt][3];
                __nv_bfloat16 h0 = __float2bfloat16(y0), h1 = __float2bfloat16(y1);
                __nv_bfloat16 h2 = __float2bfloat16(y2), h3 = __float2bfloat16(y3);
                *(uint32_t*)(smem + SB_HI + (uint32_t)r0 * SK_BYTES + (uint32_t)c * 2) = pack2(h0, h1);
                *(uint32_t*)(smem + SB_HI + (uint32_t)r1 * SK_BYTES + (uint32_t)c * 2) = pack2(h2, h3);
                *(uint32_t*)(smem + SB_LO + (uint32_t)r0 * SK_BYTES + (uint32_t)c * 2) =
                    pack2(__float2bfloat16(y0 - __bfloat162float(h0)),
                          __float2bfloat16(y1 - __bfloat162float(h1)));
                *(uint32_t*)(smem + SB_LO + (uint32_t)r1 * SK_BYTES + (uint32_t)c * 2) =
                    pack2(__float2bfloat16(y2 - __bfloat162float(h2)),
                          __float2bfloat16(y3 - __bfloat162float(h3)));
            }
        }
        uint4* az = (uint4*)(smem + SA_HI);
        for (int i = tid; i < 2176; i += 256) az[i] = make_uint4(0, 0, 0, 0);
    }
    __syncthreads();

    // packed 16-bit pair counts via int atomics (rows of 68 words = 272 B)
    {
        int* cntw = (int*)(smem + SA_HI);
        const int gb = 1 << layer, npg = NPG0 >> layer;
        const int g0 = blockIdx.x * gb;
        const int tot = gb * EPG;
        for (int idx = tid; idx < tot; idx += 256) {
            int j = idx >> 11;
            int e = (g0 + j) * EPG + (idx & 2047);
            int nb = (g0 + j) * NPG0;
            int d = (dst[e] - nb) >> layer;
            int s = (src[e] - nb) >> layer;
            int row = j * npg + d, col = j * npg + s;
            atomicAdd(&cntw[row * 68 + (col >> 1)], 1 << ((col & 1) * 16));
        }
    }
    __syncthreads();

    // counts -> bf16 Abar (+I), in place
    {
        uint32_t* cw = (uint32_t*)(smem + SA_HI);
        for (int i = tid; i < 128 * 64; i += 256) {
            int row = i >> 6, w = i & 63;
            int col = w * 2;
            uint32_t v = cw[row * 68 + w];
            float v0 = (float)(v & 0xFFFFu) + ((row == col)     ? 1.f : 0.f);
            float v1 = (float)(v >> 16)     + ((row == col + 1) ? 1.f : 0.f);
            cw[row * 68 + w] = pack2(__float2bfloat16(v0), __float2bfloat16(v1));
        }
    }
    __syncthreads();

    // agg MMA: acc2 = Abar @ (Yhi + Ylo)
    float acc2[2][8][4];
    #pragma unroll
    for (int mt = 0; mt < 2; mt++)
        #pragma unroll
        for (int nt = 0; nt < 8; nt++)
            #pragma unroll
            for (int j = 0; j < 4; j++) acc2[mt][nt][j] = 0.f;
    {
        const uint32_t aA = sb + SA_HI + (uint32_t)(wm * 32 + (lane & 15)) * SK_BYTES
                          + (uint32_t)(lane >> 4) * 16;
        const uint32_t aB = sb + SB_HI + (uint32_t)(lane & 15) * SK_BYTES
                          + (uint32_t)(wn * 128) + (uint32_t)(lane >> 4) * 16;
        #pragma unroll
        for (int ks = 0; ks < 8; ks++) {
            uint32_t a[2][4], bh[4][4], bl[4][4];
            #pragma unroll
            for (int mt = 0; mt < 2; mt++)
                LDSM_X4(a[mt], aA + (uint32_t)mt * (16 * SK_BYTES) + (uint32_t)ks * 32);
            #pragma unroll
            for (int nt2 = 0; nt2 < 4; nt2++) {
                uint32_t bd = aB + (uint32_t)ks * (16 * SK_BYTES) + (uint32_t)nt2 * 32;
                LDSM_X4T(bh[nt2], bd);
                LDSM_X4T(bl[nt2], bd + (SB_LO - SB_HI));
            }
            #pragma unroll
            for (int mt = 0; mt < 2; mt++)
                #pragma unroll
                for (int nt = 0; nt < 8; nt++) {
                    uint32_t b0h = bh[nt >> 1][(nt & 1) * 2], b1h = bh[nt >> 1][(nt & 1) * 2 + 1];
                    uint32_t b0l = bl[nt >> 1][(nt & 1) * 2], b1l = bl[nt >> 1][(nt & 1) * 2 + 1];
                    MMA_BF16(acc2[mt][nt], a[mt], b0h, b1h);
                    MMA_BF16(acc2[mt][nt], a[mt], b0l, b1l);
                }
        }
    }
    __syncthreads();
    epilogue_tile(acc2, smem, H + (size_t)blockIdx.x * 16384, wm, wn, lane);
    __syncthreads();
    if (tid < 256) atomicAdd(&statsOut[tid], ((float*)(smem + SO_STAT))[tid]);
}

// ---------------- pool: inline BN+relu -> Haar -> plane out + embd sums/stats --
__global__ __launch_bounds__(256) void pool_kernel(
    const float* __restrict__ Hin,
    const float* __restrict__ bnG, const float* __restrict__ bnB,
    const float* __restrict__ statsIn, float nIn,
    __nv_bfloat16* __restrict__ Xhi, __nv_bfloat16* __restrict__ Xlo, int writeX,
    float* __restrict__ embraw, float* __restrict__ statsOut, int npg_in) {
    __shared__ float es[128], psc[128], psh[128];
    const int g = blockIdx.x, tid = threadIdx.x;
    if (tid < 128) {
        es[tid] = 0.f;
        float sv = statsIn[tid], qv = statsIn[128 + tid];
        float m = sv / nIn, v = qv / nIn - m * m;
        float c_ = bnG[tid] * rsqrtf(v + BN_EPS);
        psc[tid] = c_;
        psh[tid] = fmaf(-m, c_, bnB[tid]);
    }
    __syncthreads();

    const int npg_out = npg_in >> 1;
    const float4* in4 = (const float4*)(Hin + (size_t)g * npg_in * 128);
    const size_t xbase = (size_t)g * npg_out * 128;

    const int cfix = (tid & 31) * 4;
    float a0 = 0.f, a1 = 0.f, a2 = 0.f, a3 = 0.f;

    for (int i = tid; i < npg_out * 32; i += 256) {
        int row = i >> 5, c = cfix;
        float4 a = in4[(2 * row) * 32 + (i & 31)];
        float4 b = in4[(2 * row + 1) * 32 + (i & 31)];
        float4 p;
        p.x = (fmaxf(fmaf(a.x, psc[c+0], psh[c+0]), 0.f) + fmaxf(fmaf(b.x, psc[c+0], psh[c+0]), 0.f)) * INV_SQRT2;
        p.y = (fmaxf(fmaf(a.y, psc[c+1], psh[c+1]), 0.f) + fmaxf(fmaf(b.y, psc[c+1], psh[c+1]), 0.f)) * INV_SQRT2;
        p.z = (fmaxf(fmaf(a.z, psc[c+2], psh[c+2]), 0.f) + fmaxf(fmaf(b.z, psc[c+2], psh[c+2]), 0.f)) * INV_SQRT2;
        p.w = (fmaxf(fmaf(a.w, psc[c+3], psh[c+3]), 0.f) + fmaxf(fmaf(b.w, psc[c+3], psh[c+3]), 0.f)) * INV_SQRT2;
        if (writeX) {
            __nv_bfloat16 hx = __float2bfloat16(p.x), hy = __float2bfloat16(p.y);
            __nv_bfloat16 hz = __float2bfloat16(p.z), hw = __float2bfloat16(p.w);
            size_t e = xbase + (size_t)row * 128 + c;
            *(uint32_t*)(Xhi + e)     = pack2(hx, hy);
            *(uint32_t*)(Xhi + e + 2) = pack2(hz, hw);
            *(uint32_t*)(Xlo + e)     = pack2(__float2bfloat16(p.x - __bfloat162float(hx)),
                                              __float2bfloat16(p.y - __bfloat162float(hy)));
            *(uint32_t*)(Xlo + e + 2) = pack2(__float2bfloat16(p.z - __bfloat162float(hz)),
                                              __float2bfloat16(p.w - __bfloat162float(hw)));
        }
        a0 += p.x; a1 += p.y; a2 += p.z; a3 += p.w;
    }
    atomicAdd(&es[cfix + 0], a0);
    atomicAdd(&es[cfix + 1], a1);
    atomicAdd(&es[cfix + 2], a2);
    atomicAdd(&es[cfix + 3], a3);
    __syncthreads();
    if (tid < 128) {
        float v = es[tid];
        embraw[g * 128 + tid] = v;
        atomicAdd(&statsOut[tid], v);
        atomicAdd(&statsOut[128 + tid], v * v);
    }
}

// ---------------- final linear with inline embedding-BN ------------------------
__global__ void final_linear_kernel(
    const float* __restrict__ embraw, const float* __restrict__ statsAll,
    const float* __restrict__ bneG, const float* __restrict__ bneB,
    const float* __restrict__ W, const float* __restrict__ b, float* __restrict__ out) {
    const int g = blockIdx.x, lane = threadIdx.x;
    float acc[C_CLASSES];
    #pragma unroll
    for (int c = 0; c < C_CLASSES; c++) acc[c] = 0.f;
    for (int k = lane; k < L_LAYERS * H_DIM; k += 32) {
        int layer = k >> 7, c = k & 127;
        const float* st = statsAll + (3 + 3 * layer) * 256;
        float m = st[c] / (float)G_GRAPHS;
        float v = st[128 + c] / (float)G_GRAPHS - m * m;
        float sc = bneG[layer * 128 + c] * rsqrtf(v + BN_EPS);
        float sh = fmaf(-m, sc, bneB[layer * 128 + c]);
        float e = fmaxf(fmaf(embraw[(size_t)layer * G_GRAPHS * 128 + g * 128 + c], sc, sh), 0.f);
        #pragma unroll
        for (int c10 = 0; c10 < C_CLASSES; c10++)
            acc[c10] = fmaf(e, W[k * C_CLASSES + c10], acc[c10]);
    }
    #pragma unroll
    for (int off = 16; off > 0; off >>= 1)
        #pragma unroll
        for (int c = 0; c < C_CLASSES; c++)
            acc[c] += __shfl_down_sync(0xFFFFFFFFu, acc[c], off);
    if (lane == 0) {
        #pragma unroll
        for (int c = 0; c < C_CLASSES; c++)
            out[g * C_CLASSES + c] = acc[c] + b[c];
    }
}

// ---------------- host orchestration ----------------
static inline int gemm_grid(int ntiles) { return ntiles < MAXCTAS ? ntiles : MAXCTAS; }

extern "C" void kernel_launch(void* const* d_in, const int* in_sizes, int n_in,
                              void* d_out, int out_size) {
    const float* x           = (const float*)d_in[0];
    const int*   ei          = (const int*)d_in[1];
    const int*   src         = ei;
    const int*   dst         = ei + E_EDGES;
    const float* lin_start_w = (const float*)d_in[2];
    const float* lin_start_b = (const float*)d_in[3];
    const float* bn_start_g  = (const float*)d_in[4];
    const float* bn_start_b  = (const float*)d_in[5];
    const float* conv_w1     = (const float*)d_in[6];
    const float* conv_b1     = (const float*)d_in[7];
    const float* conv_bn_g   = (const float*)d_in[8];
    const float* conv_bn_b   = (const float*)d_in[9];
    const float* conv_w2     = (const float*)d_in[10];
    const float* conv_b2     = (const float*)d_in[11];
    const float* bn_g        = (const float*)d_in[12];
    const float* bn_b        = (const float*)d_in[13];
    const float* bne_g       = (const float*)d_in[14];
    const float* bne_b       = (const float*)d_in[15];
    const float* lin_w       = (const float*)d_in[16];
    const float* lin_b       = (const float*)d_in[17];
    float* out = (float*)d_out;

    float *bufA, *bufB, *bufX, *embraw, *statsAll;
    __nv_bfloat16* wimg;
    cudaGetSymbolAddress((void**)&bufA,     g_bufA);
    cudaGetSymbolAddress((void**)&bufB,     g_bufB);
    cudaGetSymbolAddress((void**)&bufX,     g_X);
    cudaGetSymbolAddress((void**)&embraw,   g_embraw);
    cudaGetSymbolAddress((void**)&statsAll, g_statsAll);
    cudaGetSymbolAddress((void**)&wimg,     g_wimg);

    __nv_bfloat16* Xhi = (__nv_bfloat16*)bufX;
    __nv_bfloat16* Xlo = Xhi + XPLANE;

    cudaFuncSetAttribute(tc_gemm, cudaFuncAttributeMaxDynamicSharedMemorySize, BIG_SMEM);
    cudaFuncSetAttribute(fused_layer, cudaFuncAttributeMaxDynamicSharedMemorySize, BIG_SMEM);

    transw_kernel<<<8, 256>>>(lin_start_w, conv_w1, conv_w2, wimg, statsAll);

    float* slot0 = statsAll;

    // Stage 0: bufA = x @ W_start + b  (persistent grid-stride)
    {
        int nt0 = N_NODES / 128;
        tc_gemm<<<gemm_grid(nt0), 256, BIG_SMEM>>>(
            x, wimg, lin_start_b, nullptr, nullptr, nullptr, 0.f, 0, bufA, slot0, nt0);
    }

    for (int i = 0; i < L_LAYERS; i++) {
        const int n = N_NODES >> i;
        const int npg = NPG0 >> i;
        float* slotH = statsAll + (1 + 3 * i) * 256;
        float* slotG = statsAll + (2 + 3 * i) * 256;
        float* slotE = statsAll + (3 + 3 * i) * 256;

        // fused: H = (I+A)(op(x)@W1) + b1
        fused_layer<<<n / 128, 256, BIG_SMEM>>>(
            (i == 0) ? (const float*)bufA : nullptr,
            (i == 0) ? nullptr : Xhi, (i == 0) ? nullptr : Xlo,
            wimg + (size_t)(1 + i) * 32768, src, dst, conv_b1 + i * H_DIM,
            (i == 0) ? bn_start_g : nullptr, (i == 0) ? bn_start_b : nullptr,
            (i == 0) ? slot0 : nullptr, (float)N_NODES,
            (i == 0) ? 0 : 2, (i == 0) ? 1 : 0,
            bufA, slotH, i);

        // G = relu(bn(H)) @ W2 + b2  (persistent grid-stride)
        {
            int nt = n / 128;
            tc_gemm<<<gemm_grid(nt), 256, BIG_SMEM>>>(
                bufA, wimg + (size_t)(4 + i) * 32768, conv_b2 + i * H_DIM,
                conv_bn_g + i * H_DIM, conv_bn_b + i * H_DIM, slotH, (float)n, 1,
                bufB, slotG, nt);
        }

        // pool: bn(G)+relu -> Haar -> X planes (skip write on last layer)
        pool_kernel<<<G_GRAPHS, 256>>>(
            bufB, bn_g + i * H_DIM, bn_b + i * H_DIM, slotG, (float)n,
            Xhi, Xlo, (i < L_LAYERS - 1) ? 1 : 0,
            embraw + (size_t)i * G_GRAPHS * H_DIM, slotE, npg);
    }

    final_linear_kernel<<<G_GRAPHS, 32>>>(
        embraw, statsAll, bne_g, bne_b, lin_w, lin_b, out);
}